// round 9
// baseline (speedup 1.0000x reference)
#include <cuda_runtime.h>
#include <math.h>

#define BATCH 16384
#define B6 (BATCH*6)
#define H 128
#define DTc 0.01f
#define WARPS 15
#define TPB (WARPS*32)
#define NBLK 152

// ---- shared-memory weight layout (float offsets) ----
#define OFF_S1L 0        // [12][128]  W1L^T
#define OFF_S2L 1536     // [128][128] W2L^T (in-major)
#define OFF_S3L 17920    // [128][21]  W3L^T
#define OFF_B1L 20608
#define OFF_B2L 20736
#define OFF_B3L 20864    // 24 slots (21 used)
#define OFF_S1V 20888    // [12][128]  W1V^T
#define OFF_S2V 22424    // [128][128] W2V^T (in-major)
#define OFF_W3V 38808    // [128]
#define OFF_B1V 38936
#define OFF_B2V 39064
#define WTOT    39192
#define SCR     1228     // per-warp scratch floats (tightly packed)
#define SMEM_FLOATS (WTOT + WARPS*SCR)
#define SMEM_BYTES  (SMEM_FLOATS*4)

// per-warp scratch sublayout:
// vecs  [896]  @0
// ydy   [147]  @896
// dmj   [126]  @1043
// psm   [21]   @1169
// gsm   [6]    @1190
// rhssm [6]    @1196
// qsh   [6]    @1202
// qdsh  [6]    @1208
// tcsm  [6]    @1214
// tssm  [6]    @1220  (ends 1226)

typedef unsigned long long ull;

__device__ float g_qs[B6];
__device__ float g_qds[B6];
__device__ float g_kqd[4][B6];
__device__ unsigned g_mask[4];

__constant__ float c_LOWER[6]  = {-6.28f,-6.28f,-3.14f,-6.28f,-6.28f,-6.28f};
__constant__ float c_UPPER[6]  = { 6.28f, 6.28f, 3.14f, 6.28f, 6.28f, 6.28f};
__constant__ float c_EFFORT[6] = {150.f,150.f,150.f,28.f,28.f,28.f};
__constant__ int   c_TI[21] = {0,1,1,2,2,2,3,3,3,3,4,4,4,4,4,5,5,5,5,5,5};
__constant__ int   c_TJ[21] = {0,0,1,0,1,2,0,1,2,3,0,1,2,3,4,0,1,2,3,4,5};

// ---- packed fp32x2 helpers (Blackwell FFMA2 path) ----
__device__ __forceinline__ ull pk2(float a, float b){
    ull r; asm("mov.b64 %0, {%1, %2};" : "=l"(r) : "f"(a), "f"(b)); return r;
}
__device__ __forceinline__ void upk2(ull v, float& a, float& b){
    asm("mov.b64 {%0, %1}, %2;" : "=f"(a), "=f"(b) : "l"(v));
}
__device__ __forceinline__ ull ffma2(ull a, ull b, ull c){
    ull d; asm("fma.rn.f32x2 %0, %1, %2, %3;" : "=l"(d) : "l"(a), "l"(b), "l"(c)); return d;
}

// fast softplus + sigmoid sharing one exp
__device__ __forceinline__ void spsig(float x, float& sp, float& sg){
    float e = __expf(-fabsf(x));
    float r = __fdividef(1.0f, 1.0f + e);
    sp = fmaxf(x, 0.0f) + __logf(1.0f + e);
    sg = (x >= 0.0f) ? r : (1.0f - r);
}
__device__ __forceinline__ float sig_f(float x){
    float e = __expf(-fabsf(x));
    float r = __fdividef(1.0f, 1.0f + e);
    return (x >= 0.0f) ? r : (1.0f - r);
}
__device__ __forceinline__ float wsum(float v){
    #pragma unroll
    for (int o = 16; o; o >>= 1) v += __shfl_xor_sync(0xffffffffu, v, o);
    return v;
}

// ---------------- mask zeroing ----------------
__global__ void zeroMaskK(){
    if (threadIdx.x < 4) g_mask[threadIdx.x] = 0u;
}

// ---------------- stage state + violation mask ----------------
__global__ void stageAK(const float* __restrict__ obs, int stage){
    int e = blockIdx.x*blockDim.x + threadIdx.x;
    unsigned bits = 0u;
    if (e < BATCH){
        #pragma unroll
        for (int i = 0; i < 6; i++){
            float q  = obs[e*12 + i];
            float qd = obs[e*12 + 6 + i];
            float qs, qds;
            if (stage == 0){
                qs = q; qds = qd;
            } else if (stage == 1){
                float k1 = g_kqd[0][e*6+i];
                qs  = q + 0.5f*DTc*qd;
                qds = qd + 0.5f*DTc*k1;
            } else if (stage == 2){
                float k1 = g_kqd[0][e*6+i];
                float k2 = g_kqd[1][e*6+i];
                float k2q = qd + 0.5f*DTc*k1;
                qs  = q + 0.5f*DTc*k2q;
                qds = qd + 0.5f*DTc*k2;
            } else {
                float k2 = g_kqd[1][e*6+i];
                float k3 = g_kqd[2][e*6+i];
                float k3q = qd + 0.5f*DTc*k2;
                qs  = q + DTc*k3q;
                qds = qd + DTc*k3;
            }
            g_qs[e*6+i]  = qs;
            g_qds[e*6+i] = qds;
            float lo = c_LOWER[i] + 0.1f;
            float up = c_UPPER[i] - 0.1f;
            if (qs <= lo || qs >= up) bits |= (1u << i);
        }
    }
    if (bits) atomicOr(&g_mask[stage], bits);
}

// ---------------- heavy accel kernel ----------------
__global__ void __launch_bounds__(TPB, 1) stageBK(
    const float* __restrict__ W1L, const float* __restrict__ b1L,
    const float* __restrict__ W2L, const float* __restrict__ b2L,
    const float* __restrict__ W3L, const float* __restrict__ b3L,
    const float* __restrict__ W1V, const float* __restrict__ b1V,
    const float* __restrict__ W2V, const float* __restrict__ b2V,
    const float* __restrict__ W3V, const float* __restrict__ action,
    int stage)
{
    extern __shared__ float s[];
    const int tid = threadIdx.x;

    // stage weights (transposed to in-major) into shared
    for (int i = tid; i < 12*H; i += TPB) s[OFF_S1L + (i%12)*H + i/12] = W1L[i];
    for (int i = tid; i < H*H;  i += TPB) s[OFF_S2L + (i%H)*H + i/H]  = W2L[i];
    for (int i = tid; i < 21*H; i += TPB) s[OFF_S3L + (i%H)*21 + i/H] = W3L[i];
    for (int i = tid; i < 12*H; i += TPB) s[OFF_S1V + (i%12)*H + i/12] = W1V[i];
    for (int i = tid; i < H*H;  i += TPB) s[OFF_S2V + (i%H)*H + i/H]  = W2V[i];
    for (int i = tid; i < H; i += TPB){
        s[OFF_B1L+i]=b1L[i]; s[OFF_B2L+i]=b2L[i];
        s[OFF_B1V+i]=b1V[i]; s[OFF_B2V+i]=b2V[i];
        s[OFF_W3V+i]=W3V[i];
    }
    for (int i = tid; i < 21; i += TPB) s[OFF_B3L+i]=b3L[i];
    __syncthreads();

    const unsigned mask = g_mask[stage];
    const int wid = tid >> 5, lane = tid & 31;
    float* scr   = s + WTOT + wid*SCR;
    float* vecs  = scr;
    float* ydy   = scr + 896;
    float* dmj   = scr + 1043;
    float* psm   = scr + 1169;
    float* gsm   = scr + 1190;
    float* rhssm = scr + 1196;
    float* qsh   = scr + 1202;
    float* qdsh  = scr + 1208;
    float* tcsm  = scr + 1214;
    float* tssm  = scr + 1220;
    const int o0 = lane*4;
    float* kout = g_kqd[stage];

    for (int e = blockIdx.x*WARPS + wid; e < BATCH; e += gridDim.x*WARPS){
        if (lane < 6){
            float qv  = g_qs[e*6+lane];
            float qdv = g_qds[e*6+lane];
            qsh[lane]  = qv;
            qdsh[lane] = qdv;
            float sn, cs;
            __sincosf(qv, &sn, &cs);
            tcsm[lane] = cs;
            tssm[lane] = sn;
        }
        __syncwarp();
        float tc[6], tsn[6], qdr[6];
        #pragma unroll
        for (int i = 0; i < 6; i++){ tc[i]=tcsm[i]; tsn[i]=tssm[i]; qdr[i]=qdsh[i]; }

        // ==================== L network ====================
        // ---- layer 1: h1 + 6 tangents
        {
            float zz[4];
            #pragma unroll
            for (int m=0;m<4;m++) zz[m] = s[OFF_B1L+o0+m];
            #pragma unroll
            for (int k=0;k<12;k++){
                float tk = (k&1) ? tsn[k>>1] : tc[k>>1];
                float4 w = *(const float4*)&s[OFF_S1L + k*H + o0];
                zz[0]+=w.x*tk; zz[1]+=w.y*tk; zz[2]+=w.z*tk; zz[3]+=w.w*tk;
            }
            float s1[4];
            #pragma unroll
            for (int m=0;m<4;m++){
                float spv, sgv; spsig(zz[m], spv, sgv);
                vecs[o0+m] = spv; s1[m] = sgv;
            }
            #pragma unroll
            for (int j=0;j<6;j++){
                float4 wa = *(const float4*)&s[OFF_S1L + (2*j  )*H + o0];
                float4 wb = *(const float4*)&s[OFF_S1L + (2*j+1)*H + o0];
                float cj = tc[j], sj = tsn[j];
                vecs[(j+1)*H + o0 + 0] = s1[0]*(wb.x*cj - wa.x*sj);
                vecs[(j+1)*H + o0 + 1] = s1[1]*(wb.y*cj - wa.y*sj);
                vecs[(j+1)*H + o0 + 2] = s1[2]*(wb.z*cj - wa.z*sj);
                vecs[(j+1)*H + o0 + 3] = s1[3]*(wb.w*cj - wa.w*sj);
            }
        }
        __syncwarp();

        // ---- layer 2, fused over 7 vectors (packed fp32x2 over m-pairs)
        {
            ull a01[7], a23[7];
            a01[0] = pk2(s[OFF_B2L+o0+0], s[OFF_B2L+o0+1]);
            a23[0] = pk2(s[OFF_B2L+o0+2], s[OFF_B2L+o0+3]);
            #pragma unroll
            for (int v=1;v<7;v++){ a01[v]=0ull; a23[v]=0ull; }
            for (int k=0;k<H;k+=4){
                float4 h4[7];
                #pragma unroll
                for (int v=0;v<7;v++) h4[v] = *(const float4*)&vecs[v*H + k];
                #pragma unroll
                for (int kk=0;kk<4;kk++){
                    float4 w = *(const float4*)&s[OFF_S2L + (k+kk)*H + o0];
                    ull w01 = pk2(w.x, w.y), w23 = pk2(w.z, w.w);
                    #pragma unroll
                    for (int v=0;v<7;v++){
                        float hs = (&h4[v].x)[kk];
                        ull h2 = pk2(hs, hs);
                        a01[v] = ffma2(w01, h2, a01[v]);
                        a23[v] = ffma2(w23, h2, a23[v]);
                    }
                }
            }
            __syncwarp();
            float av[7][4];
            #pragma unroll
            for (int v=0;v<7;v++){
                upk2(a01[v], av[v][0], av[v][1]);
                upk2(a23[v], av[v][2], av[v][3]);
            }
            float s2[4];
            #pragma unroll
            for (int m=0;m<4;m++){
                float spv, sgv; spsig(av[0][m], spv, sgv);
                vecs[o0+m] = spv; s2[m] = sgv;
            }
            #pragma unroll
            for (int v=1;v<7;v++){
                #pragma unroll
                for (int m=0;m<4;m++) vecs[v*H+o0+m] = s2[m]*av[v][m];
            }
        }
        __syncwarp();

        // ---- layer 3 (21 outputs) -> y, dy_j
        if (lane < 21){
            float f7[7];
            f7[0] = s[OFF_B3L+lane];
            #pragma unroll
            for (int v=1;v<7;v++) f7[v]=0.f;
            for (int k=0;k<H;k+=4){
                float w0 = s[OFF_S3L+(k+0)*21+lane];
                float w1 = s[OFF_S3L+(k+1)*21+lane];
                float w2 = s[OFF_S3L+(k+2)*21+lane];
                float w3 = s[OFF_S3L+(k+3)*21+lane];
                #pragma unroll
                for (int v=0;v<7;v++){
                    float4 h4 = *(const float4*)&vecs[v*H + k];
                    f7[v] += w0*h4.x + w1*h4.y + w2*h4.z + w3*h4.w;
                }
            }
            float spv, s3; spsig(f7[0], spv, s3);
            ydy[lane] = spv;
            #pragma unroll
            for (int v=1;v<7;v++) ydy[v*21+lane] = s3*f7[v];
        }
        __syncwarp();

        // ==================== V network (forward-mode gradient) ====================
        // ---- layer 1: value + 6 tangents (overwrite vecs)
        {
            float zz[4];
            #pragma unroll
            for (int m=0;m<4;m++) zz[m] = s[OFF_B1V+o0+m];
            #pragma unroll
            for (int k=0;k<12;k++){
                float tk = (k&1) ? tsn[k>>1] : tc[k>>1];
                float4 w = *(const float4*)&s[OFF_S1V + k*H + o0];
                zz[0]+=w.x*tk; zz[1]+=w.y*tk; zz[2]+=w.z*tk; zz[3]+=w.w*tk;
            }
            float s1[4];
            #pragma unroll
            for (int m=0;m<4;m++){
                float spv, sgv; spsig(zz[m], spv, sgv);
                vecs[o0+m] = spv; s1[m] = sgv;
            }
            #pragma unroll
            for (int j=0;j<6;j++){
                float4 wa = *(const float4*)&s[OFF_S1V + (2*j  )*H + o0];
                float4 wb = *(const float4*)&s[OFF_S1V + (2*j+1)*H + o0];
                float cj = tc[j], sj = tsn[j];
                vecs[(j+1)*H + o0 + 0] = s1[0]*(wb.x*cj - wa.x*sj);
                vecs[(j+1)*H + o0 + 1] = s1[1]*(wb.y*cj - wa.y*sj);
                vecs[(j+1)*H + o0 + 2] = s1[2]*(wb.z*cj - wa.z*sj);
                vecs[(j+1)*H + o0 + 3] = s1[3]*(wb.w*cj - wa.w*sj);
            }
        }
        __syncwarp();

        // ---- layer 2 fused over 7 vectors (packed) + gravity dot with W3V
        {
            ull a01[7], a23[7];
            a01[0] = pk2(s[OFF_B2V+o0+0], s[OFF_B2V+o0+1]);
            a23[0] = pk2(s[OFF_B2V+o0+2], s[OFF_B2V+o0+3]);
            #pragma unroll
            for (int v=1;v<7;v++){ a01[v]=0ull; a23[v]=0ull; }
            for (int k=0;k<H;k+=4){
                float4 h4[7];
                #pragma unroll
                for (int v=0;v<7;v++) h4[v] = *(const float4*)&vecs[v*H + k];
                #pragma unroll
                for (int kk=0;kk<4;kk++){
                    float4 w = *(const float4*)&s[OFF_S2V + (k+kk)*H + o0];
                    ull w01 = pk2(w.x, w.y), w23 = pk2(w.z, w.w);
                    #pragma unroll
                    for (int v=0;v<7;v++){
                        float hs = (&h4[v].x)[kk];
                        ull h2 = pk2(hs, hs);
                        a01[v] = ffma2(w01, h2, a01[v]);
                        a23[v] = ffma2(w23, h2, a23[v]);
                    }
                }
            }
            float av[7][4];
            #pragma unroll
            for (int v=0;v<7;v++){
                upk2(a01[v], av[v][0], av[v][1]);
                upk2(a23[v], av[v][2], av[v][3]);
            }
            float pj[6];
            #pragma unroll
            for (int j=0;j<6;j++) pj[j]=0.f;
            #pragma unroll
            for (int m=0;m<4;m++){
                float wv = s[OFF_W3V+o0+m] * sig_f(av[0][m]);
                #pragma unroll
                for (int j=0;j<6;j++) pj[j] += wv*av[j+1][m];
            }
            #pragma unroll
            for (int j=0;j<6;j++){
                float g = wsum(pj[j]);
                if (lane == 0) gsm[j] = g;
            }
        }
        __syncwarp();

        // ---- dM_j lower-tri entries
        for (int t = lane; t < 126; t += 32){
            int j = t/21, u = t%21;
            int a = c_TI[u], b = c_TJ[u];
            int ta = a*(a+1)/2, tb = b*(b+1)/2;
            const float* Lr = ydy;
            const float* Dr = ydy + (j+1)*21;
            float sacc = 0.f;
            for (int m = 0; m <= b; m++)
                sacc += Dr[ta+m]*Lr[tb+m] + Lr[ta+m]*Dr[tb+m];
            dmj[t] = sacc;
        }
        __syncwarp();

        // ---- P = sum_j qdot_j dM_j
        if (lane < 21){
            float p = 0.f;
            #pragma unroll
            for (int j=0;j<6;j++) p += qdr[j]*dmj[j*21+lane];
            psm[lane] = p;
        }
        __syncwarp();

        // ---- c_i, constraints, rhs
        if (lane < 6){
            int i = lane;
            float c1 = 0.f;
            #pragma unroll
            for (int b=0;b<6;b++){
                int idx = (i >= b) ? (i*(i+1)/2 + b) : (b*(b+1)/2 + i);
                c1 += psm[idx]*qdr[b];
            }
            float qf = 0.f;   // 0.5 * qd^T dM_i qd
            for (int u2=0; u2<21; u2++){
                int a = c_TI[u2], b = c_TJ[u2];
                float w = (a==b) ? 0.5f : 1.0f;
                qf += w*dmj[i*21+u2]*qdsh[a]*qdsh[b];
            }
            float ci = c1 - qf;
            float qi = qsh[i];
            float lo = c_LOWER[i] + 0.1f;
            float up = c_UPPER[i] - 0.1f;
            float fi;
            if (mask & (1u << i))
                fi = (qi <= lo) ? c_EFFORT[i] : ((qi >= up) ? -c_EFFORT[i] : 0.0f);
            else
                fi = -5.0f*(__fdividef(1.0f, qi-lo) - __fdividef(1.0f, up-qi));
            float tau = action[e*6+i]*c_EFFORT[i];
            rhssm[i] = tau - ci - gsm[i] - fi;
        }
        __syncwarp();

        // ---- solve (L L^T) x = rhs via fwd/back substitution
        if (lane == 0){
            float Lm[6][6];
            #pragma unroll
            for (int i=0;i<6;i++){
                #pragma unroll
                for (int jj=0;jj<6;jj++)
                    Lm[i][jj] = (jj<=i) ? ydy[i*(i+1)/2+jj] : 0.f;
            }
            float rinv[6];
            #pragma unroll
            for (int i=0;i<6;i++) rinv[i] = __fdividef(1.0f, Lm[i][i]);
            float wv[6], x[6];
            #pragma unroll
            for (int i=0;i<6;i++){
                float sr = rhssm[i];
                #pragma unroll
                for (int jj=0;jj<6;jj++) if (jj < i) sr -= Lm[i][jj]*wv[jj];
                wv[i] = sr * rinv[i];
            }
            #pragma unroll
            for (int i=5;i>=0;i--){
                float sr = wv[i];
                #pragma unroll
                for (int jj=0;jj<6;jj++) if (jj > i) sr -= Lm[jj][i]*x[jj];
                x[i] = sr * rinv[i];
            }
            #pragma unroll
            for (int i=0;i<6;i++) kout[e*6+i] = x[i];
        }
        __syncwarp();
    }
}

// ---------------- final RK4 combine ----------------
__global__ void stageFK(const float* __restrict__ obs, float* __restrict__ out){
    int e = blockIdx.x*blockDim.x + threadIdx.x;
    if (e >= BATCH) return;
    #pragma unroll
    for (int i=0;i<6;i++){
        float q  = obs[e*12 + i];
        float qd = obs[e*12 + 6 + i];
        float k1 = g_kqd[0][e*6+i];
        float k2 = g_kqd[1][e*6+i];
        float k3 = g_kqd[2][e*6+i];
        float k4 = g_kqd[3][e*6+i];
        float k1q = qd;
        float k2q = qd + 0.5f*DTc*k1;
        float k3q = qd + 0.5f*DTc*k2;
        float k4q = qd + DTc*k3;
        float qn  = q  + (DTc/6.0f)*(k1q + 2.f*k2q + 2.f*k3q + k4q);
        float qdn = qd + (DTc/6.0f)*(k1  + 2.f*k2  + 2.f*k3  + k4 );
        qn = fminf(fmaxf(qn, c_LOWER[i]), c_UPPER[i]);
        out[e*12 + i]     = qn;
        out[e*12 + 6 + i] = qdn;
    }
}

extern "C" void kernel_launch(void* const* d_in, const int* in_sizes, int n_in,
                              void* d_out, int out_size)
{
    const float* obs    = (const float*)d_in[0];
    const float* action = (const float*)d_in[1];
    const float* W1L = (const float*)d_in[2];  const float* b1L = (const float*)d_in[3];
    const float* W2L = (const float*)d_in[4];  const float* b2L = (const float*)d_in[5];
    const float* W3L = (const float*)d_in[6];  const float* b3L = (const float*)d_in[7];
    const float* W1V = (const float*)d_in[8];  const float* b1V = (const float*)d_in[9];
    const float* W2V = (const float*)d_in[10]; const float* b2V = (const float*)d_in[11];
    const float* W3V = (const float*)d_in[12];
    float* out = (float*)d_out;

    cudaFuncSetAttribute(stageBK, cudaFuncAttributeMaxDynamicSharedMemorySize, SMEM_BYTES);

    zeroMaskK<<<1, 32>>>();
    for (int st = 0; st < 4; st++){
        stageAK<<<BATCH/256, 256>>>(obs, st);
        stageBK<<<NBLK, TPB, SMEM_BYTES>>>(W1L,b1L,W2L,b2L,W3L,b3L,
                                           W1V,b1V,W2V,b2V,W3V, action, st);
    }
    stageFK<<<BATCH/256, 256>>>(obs, out);
}

// round 10
// speedup vs baseline: 1.0120x; 1.0120x over previous
#include <cuda_runtime.h>
#include <math.h>

#define BATCH 16384
#define B6 (BATCH*6)
#define H 128
#define DTc 0.01f
#define WARPS 14
#define TPB (WARPS*32)
#define NBLK 152

// ---- shared-memory weight layout (float offsets) ----
#define OFF_S1L 0        // [12][128]  W1L^T
#define OFF_S2L 1536     // [128][128] W2L^T (in-major)
#define OFF_S3L 17920    // [128][21]  W3L^T
#define OFF_B1L 20608
#define OFF_B2L 20736
#define OFF_B3L 20864    // 24 slots (21 used)
#define OFF_S1V 20888    // [12][128]  W1V^T
#define OFF_S2V 22424    // [128][128] W2V^T (in-major)
#define OFF_W3V 38808    // [128]
#define OFF_B1V 38936
#define OFF_B2V 39064
#define WTOT    39192
#define SCR     1228     // per-warp scratch floats (tightly packed)
#define SMEM_FLOATS (WTOT + WARPS*SCR)
#define SMEM_BYTES  (SMEM_FLOATS*4)

// per-warp scratch sublayout:
// vecs  [896]  @0    : value[128] + 3 pair-rows[256] (tangents interleaved)
// ydy   [147]  @896
// dmj   [126]  @1043
// psm   [21]   @1169
// gsm   [6]    @1190
// rhssm [6]    @1196
// qsh   [6]    @1202
// qdsh  [6]    @1208
// tcsm  [6]    @1214
// tssm  [6]    @1220

typedef unsigned long long ull;

__device__ float g_qs[B6];
__device__ float g_qds[B6];
__device__ float g_kqd[4][B6];
__device__ unsigned g_mask[4];

__constant__ float c_LOWER[6]  = {-6.28f,-6.28f,-3.14f,-6.28f,-6.28f,-6.28f};
__constant__ float c_UPPER[6]  = { 6.28f, 6.28f, 3.14f, 6.28f, 6.28f, 6.28f};
__constant__ float c_EFFORT[6] = {150.f,150.f,150.f,28.f,28.f,28.f};
__constant__ int   c_TI[21] = {0,1,1,2,2,2,3,3,3,3,4,4,4,4,4,5,5,5,5,5,5};
__constant__ int   c_TJ[21] = {0,0,1,0,1,2,0,1,2,3,0,1,2,3,4,0,1,2,3,4,5};

// ---- packed fp32x2 helpers ----
__device__ __forceinline__ ull pk2(float a, float b){
    ull r; asm("mov.b64 %0, {%1, %2};" : "=l"(r) : "f"(a), "f"(b)); return r;
}
__device__ __forceinline__ void upk2(ull v, float& a, float& b){
    asm("mov.b64 {%0, %1}, %2;" : "=f"(a), "=f"(b) : "l"(v));
}
__device__ __forceinline__ ull ffma2(ull a, ull b, ull c){
    ull d; asm("fma.rn.f32x2 %0, %1, %2, %3;" : "=l"(d) : "l"(a), "l"(b), "l"(c)); return d;
}

// fast softplus + sigmoid sharing one exp
__device__ __forceinline__ void spsig(float x, float& sp, float& sg){
    float e = __expf(-fabsf(x));
    float r = __fdividef(1.0f, 1.0f + e);
    sp = fmaxf(x, 0.0f) + __logf(1.0f + e);
    sg = (x >= 0.0f) ? r : (1.0f - r);
}
__device__ __forceinline__ float sig_f(float x){
    float e = __expf(-fabsf(x));
    float r = __fdividef(1.0f, 1.0f + e);
    return (x >= 0.0f) ? r : (1.0f - r);
}
__device__ __forceinline__ float wsum(float v){
    #pragma unroll
    for (int o = 16; o; o >>= 1) v += __shfl_xor_sync(0xffffffffu, v, o);
    return v;
}

// ---------------- mask zeroing ----------------
__global__ void zeroMaskK(){
    if (threadIdx.x < 4) g_mask[threadIdx.x] = 0u;
}

// ---------------- stage state + violation mask ----------------
__global__ void stageAK(const float* __restrict__ obs, int stage){
    int e = blockIdx.x*blockDim.x + threadIdx.x;
    unsigned bits = 0u;
    if (e < BATCH){
        #pragma unroll
        for (int i = 0; i < 6; i++){
            float q  = obs[e*12 + i];
            float qd = obs[e*12 + 6 + i];
            float qs, qds;
            if (stage == 0){
                qs = q; qds = qd;
            } else if (stage == 1){
                float k1 = g_kqd[0][e*6+i];
                qs  = q + 0.5f*DTc*qd;
                qds = qd + 0.5f*DTc*k1;
            } else if (stage == 2){
                float k1 = g_kqd[0][e*6+i];
                float k2 = g_kqd[1][e*6+i];
                float k2q = qd + 0.5f*DTc*k1;
                qs  = q + 0.5f*DTc*k2q;
                qds = qd + 0.5f*DTc*k2;
            } else {
                float k2 = g_kqd[1][e*6+i];
                float k3 = g_kqd[2][e*6+i];
                float k3q = qd + 0.5f*DTc*k2;
                qs  = q + DTc*k3q;
                qds = qd + DTc*k3;
            }
            g_qs[e*6+i]  = qs;
            g_qds[e*6+i] = qds;
            float lo = c_LOWER[i] + 0.1f;
            float up = c_UPPER[i] - 0.1f;
            if (qs <= lo || qs >= up) bits |= (1u << i);
        }
    }
    if (bits) atomicOr(&g_mask[stage], bits);
}

// ---------------- heavy accel kernel ----------------
__global__ void __launch_bounds__(TPB, 1) stageBK(
    const float* __restrict__ W1L, const float* __restrict__ b1L,
    const float* __restrict__ W2L, const float* __restrict__ b2L,
    const float* __restrict__ W3L, const float* __restrict__ b3L,
    const float* __restrict__ W1V, const float* __restrict__ b1V,
    const float* __restrict__ W2V, const float* __restrict__ b2V,
    const float* __restrict__ W3V, const float* __restrict__ action,
    int stage)
{
    extern __shared__ float s[];
    const int tid = threadIdx.x;

    // stage weights (transposed to in-major) into shared
    for (int i = tid; i < 12*H; i += TPB) s[OFF_S1L + (i%12)*H + i/12] = W1L[i];
    for (int i = tid; i < H*H;  i += TPB) s[OFF_S2L + (i%H)*H + i/H]  = W2L[i];
    for (int i = tid; i < 21*H; i += TPB) s[OFF_S3L + (i%H)*21 + i/H] = W3L[i];
    for (int i = tid; i < 12*H; i += TPB) s[OFF_S1V + (i%12)*H + i/12] = W1V[i];
    for (int i = tid; i < H*H;  i += TPB) s[OFF_S2V + (i%H)*H + i/H]  = W2V[i];
    for (int i = tid; i < H; i += TPB){
        s[OFF_B1L+i]=b1L[i]; s[OFF_B2L+i]=b2L[i];
        s[OFF_B1V+i]=b1V[i]; s[OFF_B2V+i]=b2V[i];
        s[OFF_W3V+i]=W3V[i];
    }
    for (int i = tid; i < 21; i += TPB) s[OFF_B3L+i]=b3L[i];
    __syncthreads();

    const unsigned mask = g_mask[stage];
    const int wid = tid >> 5, lane = tid & 31;
    float* scr   = s + WTOT + wid*SCR;
    float* vecs  = scr;
    float* ydy   = scr + 896;
    float* dmj   = scr + 1043;
    float* psm   = scr + 1169;
    float* gsm   = scr + 1190;
    float* rhssm = scr + 1196;
    float* qsh   = scr + 1202;
    float* qdsh  = scr + 1208;
    float* tcsm  = scr + 1214;
    float* tssm  = scr + 1220;
    const int o0 = lane*4;
    float* kout = g_kqd[stage];

    for (int e = blockIdx.x*WARPS + wid; e < BATCH; e += gridDim.x*WARPS){
        if (lane < 6){
            float qv  = g_qs[e*6+lane];
            float qdv = g_qds[e*6+lane];
            qsh[lane]  = qv;
            qdsh[lane] = qdv;
            float sn, cs;
            __sincosf(qv, &sn, &cs);
            tcsm[lane] = cs;
            tssm[lane] = sn;
        }
        __syncwarp();
        float tc[6], tsn[6], qdr[6];
        #pragma unroll
        for (int i = 0; i < 6; i++){ tc[i]=tcsm[i]; tsn[i]=tssm[i]; qdr[i]=qdsh[i]; }

        // ==================== L network ====================
        // ---- layer 1: value + 6 tangents (pair-interleaved layout)
        {
            float zz[4];
            #pragma unroll
            for (int m=0;m<4;m++) zz[m] = s[OFF_B1L+o0+m];
            #pragma unroll
            for (int k=0;k<12;k++){
                float tk = (k&1) ? tsn[k>>1] : tc[k>>1];
                float4 w = *(const float4*)&s[OFF_S1L + k*H + o0];
                zz[0]+=w.x*tk; zz[1]+=w.y*tk; zz[2]+=w.z*tk; zz[3]+=w.w*tk;
            }
            float s1[4];
            #pragma unroll
            for (int m=0;m<4;m++){
                float spv, sgv; spsig(zz[m], spv, sgv);
                vecs[o0+m] = spv; s1[m] = sgv;
            }
            #pragma unroll
            for (int p=0;p<3;p++){
                int ja = 2*p, jb = 2*p+1;
                float4 waA = *(const float4*)&s[OFF_S1L + (2*ja  )*H + o0];
                float4 wbA = *(const float4*)&s[OFF_S1L + (2*ja+1)*H + o0];
                float4 waB = *(const float4*)&s[OFF_S1L + (2*jb  )*H + o0];
                float4 wbB = *(const float4*)&s[OFF_S1L + (2*jb+1)*H + o0];
                float ca=tc[ja], sa=tsn[ja], cb=tc[jb], sb=tsn[jb];
                float tav[4], tbv[4];
                tav[0]=s1[0]*(wbA.x*ca - waA.x*sa); tbv[0]=s1[0]*(wbB.x*cb - waB.x*sb);
                tav[1]=s1[1]*(wbA.y*ca - waA.y*sa); tbv[1]=s1[1]*(wbB.y*cb - waB.y*sb);
                tav[2]=s1[2]*(wbA.z*ca - waA.z*sa); tbv[2]=s1[2]*(wbB.z*cb - waB.z*sb);
                tav[3]=s1[3]*(wbA.w*ca - waA.w*sa); tbv[3]=s1[3]*(wbB.w*cb - waB.w*sb);
                *(float4*)&vecs[128 + p*256 + 2*o0]     = make_float4(tav[0],tbv[0],tav[1],tbv[1]);
                *(float4*)&vecs[128 + p*256 + 2*o0 + 4] = make_float4(tav[2],tbv[2],tav[3],tbv[3]);
            }
        }
        __syncwarp();

        // ---- layer 2: value scalar + 3 tangent-pair FFMA2 accumulators
        {
            float a0[4];
            #pragma unroll
            for (int m=0;m<4;m++) a0[m] = s[OFF_B2L+o0+m];
            ull accp[3][4];
            #pragma unroll
            for (int p=0;p<3;p++){
                #pragma unroll
                for (int m=0;m<4;m++) accp[p][m]=0ull;
            }
            for (int k=0;k<H;k+=4){
                float4 hval = *(const float4*)&vecs[k];
                ulonglong2 hA[3], hB[3];
                #pragma unroll
                for (int p=0;p<3;p++){
                    hA[p] = *(const ulonglong2*)&vecs[128 + p*256 + 2*k];
                    hB[p] = *(const ulonglong2*)&vecs[128 + p*256 + 2*k + 4];
                }
                #pragma unroll
                for (int kk=0;kk<4;kk++){
                    float4 w = *(const float4*)&s[OFF_S2L + (k+kk)*H + o0];
                    float hs = (&hval.x)[kk];
                    a0[0] += w.x*hs; a0[1] += w.y*hs; a0[2] += w.z*hs; a0[3] += w.w*hs;
                    ull hp0 = (kk==0)? hA[0].x : (kk==1)? hA[0].y : (kk==2)? hB[0].x : hB[0].y;
                    ull hp1 = (kk==0)? hA[1].x : (kk==1)? hA[1].y : (kk==2)? hB[1].x : hB[1].y;
                    ull hp2 = (kk==0)? hA[2].x : (kk==1)? hA[2].y : (kk==2)? hB[2].x : hB[2].y;
                    #pragma unroll
                    for (int m=0;m<4;m++){
                        float wm = (&w.x)[m];
                        ull wd = pk2(wm, wm);
                        accp[0][m] = ffma2(wd, hp0, accp[0][m]);
                        accp[1][m] = ffma2(wd, hp1, accp[1][m]);
                        accp[2][m] = ffma2(wd, hp2, accp[2][m]);
                    }
                }
            }
            __syncwarp();
            float s2[4];
            #pragma unroll
            for (int m=0;m<4;m++){
                float spv, sgv; spsig(a0[m], spv, sgv);
                vecs[o0+m] = spv; s2[m] = sgv;
            }
            #pragma unroll
            for (int p=0;p<3;p++){
                float tav[4], tbv[4];
                #pragma unroll
                for (int m=0;m<4;m++){
                    float xa, xb; upk2(accp[p][m], xa, xb);
                    tav[m] = s2[m]*xa; tbv[m] = s2[m]*xb;
                }
                *(float4*)&vecs[128 + p*256 + 2*o0]     = make_float4(tav[0],tbv[0],tav[1],tbv[1]);
                *(float4*)&vecs[128 + p*256 + 2*o0 + 4] = make_float4(tav[2],tbv[2],tav[3],tbv[3]);
            }
        }
        __syncwarp();

        // ---- layer 3 (21 outputs) -> y, dy_j
        if (lane < 21){
            float f7[7];
            f7[0] = s[OFF_B3L+lane];
            #pragma unroll
            for (int v=1;v<7;v++) f7[v]=0.f;
            for (int k=0;k<H;k+=4){
                float w0 = s[OFF_S3L+(k+0)*21+lane];
                float w1 = s[OFF_S3L+(k+1)*21+lane];
                float w2 = s[OFF_S3L+(k+2)*21+lane];
                float w3 = s[OFF_S3L+(k+3)*21+lane];
                float4 h4 = *(const float4*)&vecs[k];
                f7[0] += w0*h4.x + w1*h4.y + w2*h4.z + w3*h4.w;
                #pragma unroll
                for (int p=0;p<3;p++){
                    float4 g0 = *(const float4*)&vecs[128 + p*256 + 2*k];
                    float4 g1 = *(const float4*)&vecs[128 + p*256 + 2*k + 4];
                    f7[1+2*p] += w0*g0.x + w1*g0.z + w2*g1.x + w3*g1.z;
                    f7[2+2*p] += w0*g0.y + w1*g0.w + w2*g1.y + w3*g1.w;
                }
            }
            float spv, s3; spsig(f7[0], spv, s3);
            ydy[lane] = spv;
            #pragma unroll
            for (int v=1;v<7;v++) ydy[v*21+lane] = s3*f7[v];
        }
        __syncwarp();

        // ==================== V network (forward-mode gradient) ====================
        // ---- layer 1 (pair layout, overwrite vecs)
        {
            float zz[4];
            #pragma unroll
            for (int m=0;m<4;m++) zz[m] = s[OFF_B1V+o0+m];
            #pragma unroll
            for (int k=0;k<12;k++){
                float tk = (k&1) ? tsn[k>>1] : tc[k>>1];
                float4 w = *(const float4*)&s[OFF_S1V + k*H + o0];
                zz[0]+=w.x*tk; zz[1]+=w.y*tk; zz[2]+=w.z*tk; zz[3]+=w.w*tk;
            }
            float s1[4];
            #pragma unroll
            for (int m=0;m<4;m++){
                float spv, sgv; spsig(zz[m], spv, sgv);
                vecs[o0+m] = spv; s1[m] = sgv;
            }
            #pragma unroll
            for (int p=0;p<3;p++){
                int ja = 2*p, jb = 2*p+1;
                float4 waA = *(const float4*)&s[OFF_S1V + (2*ja  )*H + o0];
                float4 wbA = *(const float4*)&s[OFF_S1V + (2*ja+1)*H + o0];
                float4 waB = *(const float4*)&s[OFF_S1V + (2*jb  )*H + o0];
                float4 wbB = *(const float4*)&s[OFF_S1V + (2*jb+1)*H + o0];
                float ca=tc[ja], sa=tsn[ja], cb=tc[jb], sb=tsn[jb];
                float tav[4], tbv[4];
                tav[0]=s1[0]*(wbA.x*ca - waA.x*sa); tbv[0]=s1[0]*(wbB.x*cb - waB.x*sb);
                tav[1]=s1[1]*(wbA.y*ca - waA.y*sa); tbv[1]=s1[1]*(wbB.y*cb - waB.y*sb);
                tav[2]=s1[2]*(wbA.z*ca - waA.z*sa); tbv[2]=s1[2]*(wbB.z*cb - waB.z*sb);
                tav[3]=s1[3]*(wbA.w*ca - waA.w*sa); tbv[3]=s1[3]*(wbB.w*cb - waB.w*sb);
                *(float4*)&vecs[128 + p*256 + 2*o0]     = make_float4(tav[0],tbv[0],tav[1],tbv[1]);
                *(float4*)&vecs[128 + p*256 + 2*o0 + 4] = make_float4(tav[2],tbv[2],tav[3],tbv[3]);
            }
        }
        __syncwarp();

        // ---- layer 2 + gravity
        {
            float a0[4];
            #pragma unroll
            for (int m=0;m<4;m++) a0[m] = s[OFF_B2V+o0+m];
            ull accp[3][4];
            #pragma unroll
            for (int p=0;p<3;p++){
                #pragma unroll
                for (int m=0;m<4;m++) accp[p][m]=0ull;
            }
            for (int k=0;k<H;k+=4){
                float4 hval = *(const float4*)&vecs[k];
                ulonglong2 hA[3], hB[3];
                #pragma unroll
                for (int p=0;p<3;p++){
                    hA[p] = *(const ulonglong2*)&vecs[128 + p*256 + 2*k];
                    hB[p] = *(const ulonglong2*)&vecs[128 + p*256 + 2*k + 4];
                }
                #pragma unroll
                for (int kk=0;kk<4;kk++){
                    float4 w = *(const float4*)&s[OFF_S2V + (k+kk)*H + o0];
                    float hs = (&hval.x)[kk];
                    a0[0] += w.x*hs; a0[1] += w.y*hs; a0[2] += w.z*hs; a0[3] += w.w*hs;
                    ull hp0 = (kk==0)? hA[0].x : (kk==1)? hA[0].y : (kk==2)? hB[0].x : hB[0].y;
                    ull hp1 = (kk==0)? hA[1].x : (kk==1)? hA[1].y : (kk==2)? hB[1].x : hB[1].y;
                    ull hp2 = (kk==0)? hA[2].x : (kk==1)? hA[2].y : (kk==2)? hB[2].x : hB[2].y;
                    #pragma unroll
                    for (int m=0;m<4;m++){
                        float wm = (&w.x)[m];
                        ull wd = pk2(wm, wm);
                        accp[0][m] = ffma2(wd, hp0, accp[0][m]);
                        accp[1][m] = ffma2(wd, hp1, accp[1][m]);
                        accp[2][m] = ffma2(wd, hp2, accp[2][m]);
                    }
                }
            }
            float pj[6];
            #pragma unroll
            for (int j=0;j<6;j++) pj[j]=0.f;
            #pragma unroll
            for (int m=0;m<4;m++){
                float wv = s[OFF_W3V+o0+m] * sig_f(a0[m]);
                #pragma unroll
                for (int p=0;p<3;p++){
                    float xa, xb; upk2(accp[p][m], xa, xb);
                    pj[2*p]   += wv*xa;
                    pj[2*p+1] += wv*xb;
                }
            }
            #pragma unroll
            for (int j=0;j<6;j++){
                float g = wsum(pj[j]);
                if (lane == 0) gsm[j] = g;
            }
        }
        __syncwarp();

        // ---- dM_j lower-tri entries
        for (int t = lane; t < 126; t += 32){
            int j = t/21, u = t%21;
            int a = c_TI[u], b = c_TJ[u];
            int ta = a*(a+1)/2, tb = b*(b+1)/2;
            const float* Lr = ydy;
            const float* Dr = ydy + (j+1)*21;
            float sacc = 0.f;
            for (int m = 0; m <= b; m++)
                sacc += Dr[ta+m]*Lr[tb+m] + Lr[ta+m]*Dr[tb+m];
            dmj[t] = sacc;
        }
        __syncwarp();

        // ---- P = sum_j qdot_j dM_j
        if (lane < 21){
            float p = 0.f;
            #pragma unroll
            for (int j=0;j<6;j++) p += qdr[j]*dmj[j*21+lane];
            psm[lane] = p;
        }
        __syncwarp();

        // ---- c_i, constraints, rhs
        if (lane < 6){
            int i = lane;
            float c1 = 0.f;
            #pragma unroll
            for (int b=0;b<6;b++){
                int idx = (i >= b) ? (i*(i+1)/2 + b) : (b*(b+1)/2 + i);
                c1 += psm[idx]*qdr[b];
            }
            float qf = 0.f;   // 0.5 * qd^T dM_i qd
            for (int u2=0; u2<21; u2++){
                int a = c_TI[u2], b = c_TJ[u2];
                float w = (a==b) ? 0.5f : 1.0f;
                qf += w*dmj[i*21+u2]*qdsh[a]*qdsh[b];
            }
            float ci = c1 - qf;
            float qi = qsh[i];
            float lo = c_LOWER[i] + 0.1f;
            float up = c_UPPER[i] - 0.1f;
            float fi;
            if (mask & (1u << i))
                fi = (qi <= lo) ? c_EFFORT[i] : ((qi >= up) ? -c_EFFORT[i] : 0.0f);
            else
                fi = -5.0f*(__fdividef(1.0f, qi-lo) - __fdividef(1.0f, up-qi));
            float tau = action[e*6+i]*c_EFFORT[i];
            rhssm[i] = tau - ci - gsm[i] - fi;
        }
        __syncwarp();

        // ---- solve (L L^T) x = rhs via fwd/back substitution
        if (lane == 0){
            float Lm[6][6];
            #pragma unroll
            for (int i=0;i<6;i++){
                #pragma unroll
                for (int jj=0;jj<6;jj++)
                    Lm[i][jj] = (jj<=i) ? ydy[i*(i+1)/2+jj] : 0.f;
            }
            float rinv[6];
            #pragma unroll
            for (int i=0;i<6;i++) rinv[i] = __fdividef(1.0f, Lm[i][i]);
            float wv[6], x[6];
            #pragma unroll
            for (int i=0;i<6;i++){
                float sr = rhssm[i];
                #pragma unroll
                for (int jj=0;jj<6;jj++) if (jj < i) sr -= Lm[i][jj]*wv[jj];
                wv[i] = sr * rinv[i];
            }
            #pragma unroll
            for (int i=5;i>=0;i--){
                float sr = wv[i];
                #pragma unroll
                for (int jj=0;jj<6;jj++) if (jj > i) sr -= Lm[jj][i]*x[jj];
                x[i] = sr * rinv[i];
            }
            #pragma unroll
            for (int i=0;i<6;i++) kout[e*6+i] = x[i];
        }
        __syncwarp();
    }
}

// ---------------- final RK4 combine ----------------
__global__ void stageFK(const float* __restrict__ obs, float* __restrict__ out){
    int e = blockIdx.x*blockDim.x + threadIdx.x;
    if (e >= BATCH) return;
    #pragma unroll
    for (int i=0;i<6;i++){
        float q  = obs[e*12 + i];
        float qd = obs[e*12 + 6 + i];
        float k1 = g_kqd[0][e*6+i];
        float k2 = g_kqd[1][e*6+i];
        float k3 = g_kqd[2][e*6+i];
        float k4 = g_kqd[3][e*6+i];
        float k1q = qd;
        float k2q = qd + 0.5f*DTc*k1;
        float k3q = qd + 0.5f*DTc*k2;
        float k4q = qd + DTc*k3;
        float qn  = q  + (DTc/6.0f)*(k1q + 2.f*k2q + 2.f*k3q + k4q);
        float qdn = qd + (DTc/6.0f)*(k1  + 2.f*k2  + 2.f*k3  + k4 );
        qn = fminf(fmaxf(qn, c_LOWER[i]), c_UPPER[i]);
        out[e*12 + i]     = qn;
        out[e*12 + 6 + i] = qdn;
    }
}

extern "C" void kernel_launch(void* const* d_in, const int* in_sizes, int n_in,
                              void* d_out, int out_size)
{
    const float* obs    = (const float*)d_in[0];
    const float* action = (const float*)d_in[1];
    const float* W1L = (const float*)d_in[2];  const float* b1L = (const float*)d_in[3];
    const float* W2L = (const float*)d_in[4];  const float* b2L = (const float*)d_in[5];
    const float* W3L = (const float*)d_in[6];  const float* b3L = (const float*)d_in[7];
    const float* W1V = (const float*)d_in[8];  const float* b1V = (const float*)d_in[9];
    const float* W2V = (const float*)d_in[10]; const float* b2V = (const float*)d_in[11];
    const float* W3V = (const float*)d_in[12];
    float* out = (float*)d_out;

    cudaFuncSetAttribute(stageBK, cudaFuncAttributeMaxDynamicSharedMemorySize, SMEM_BYTES);

    zeroMaskK<<<1, 32>>>();
    for (int st = 0; st < 4; st++){
        stageAK<<<BATCH/256, 256>>>(obs, st);
        stageBK<<<NBLK, TPB, SMEM_BYTES>>>(W1L,b1L,W2L,b2L,W3L,b3L,
                                           W1V,b1V,W2V,b2V,W3V, action, st);
    }
    stageFK<<<BATCH/256, 256>>>(obs, out);
}

// round 13
// speedup vs baseline: 1.0148x; 1.0028x over previous
#include <cuda_runtime.h>
#include <math.h>

#define BATCH 16384
#define B6 (BATCH*6)
#define H 128
#define DTc 0.01f
#define WARPS 14
#define TPB (WARPS*32)
#define NBLK 152

// ---- shared-memory weight layout (float offsets) ----
#define OFF_S1L 0        // [12][128]  W1L^T
#define OFF_S2L 1536     // [128][128] W2L^T (in-major)
#define OFF_S3L 17920    // [128][21]  W3L^T
#define OFF_B1L 20608
#define OFF_B2L 20736
#define OFF_B3L 20864    // 24 slots (21 used)
#define OFF_S1V 20888    // [12][128]  W1V^T
#define OFF_S2V 22424    // [128][128] W2V^T (in-major)
#define OFF_W3V 38808    // [128]
#define OFF_B1V 38936
#define OFF_B2V 39064
#define WTOT    39192
#define SCR     1228     // per-warp scratch floats (tightly packed)
#define SMEM_FLOATS (WTOT + WARPS*SCR)
#define SMEM_BYTES  (SMEM_FLOATS*4)

// per-warp scratch sublayout:
// vecs  [896]  @0    : value[128] + 3 pair-rows[256] (tangents interleaved)
// ydy   [147]  @896
// dmj   [126]  @1043
// psm   [21]   @1169
// gsm   [6]    @1190
// rhssm [6]    @1196
// qsh   [6]    @1202
// qdsh  [6]    @1208
// tcsm  [6]    @1214
// tssm  [6]    @1220

typedef unsigned long long ull;

__device__ float g_qs[B6];
__device__ float g_qds[B6];
__device__ float g_kqd[4][B6];
__device__ unsigned g_mask[4];

__constant__ float c_LOWER[6]  = {-6.28f,-6.28f,-3.14f,-6.28f,-6.28f,-6.28f};
__constant__ float c_UPPER[6]  = { 6.28f, 6.28f, 3.14f, 6.28f, 6.28f, 6.28f};
__constant__ float c_EFFORT[6] = {150.f,150.f,150.f,28.f,28.f,28.f};
__constant__ int   c_TI[21] = {0,1,1,2,2,2,3,3,3,3,4,4,4,4,4,5,5,5,5,5,5};
__constant__ int   c_TJ[21] = {0,0,1,0,1,2,0,1,2,3,0,1,2,3,4,0,1,2,3,4,5};

// ---- packed fp32x2 helpers ----
__device__ __forceinline__ ull pk2(float a, float b){
    ull r; asm("mov.b64 %0, {%1, %2};" : "=l"(r) : "f"(a), "f"(b)); return r;
}
__device__ __forceinline__ void upk2(ull v, float& a, float& b){
    asm("mov.b64 {%0, %1}, %2;" : "=f"(a), "=f"(b) : "l"(v));
}
__device__ __forceinline__ ull ffma2(ull a, ull b, ull c){
    ull d; asm("fma.rn.f32x2 %0, %1, %2, %3;" : "=l"(d) : "l"(a), "l"(b), "l"(c)); return d;
}

// fast softplus + sigmoid sharing one exp
__device__ __forceinline__ void spsig(float x, float& sp, float& sg){
    float e = __expf(-fabsf(x));
    float r = __fdividef(1.0f, 1.0f + e);
    sp = fmaxf(x, 0.0f) + __logf(1.0f + e);
    sg = (x >= 0.0f) ? r : (1.0f - r);
}
__device__ __forceinline__ float sig_f(float x){
    float e = __expf(-fabsf(x));
    float r = __fdividef(1.0f, 1.0f + e);
    return (x >= 0.0f) ? r : (1.0f - r);
}
__device__ __forceinline__ float wsum(float v){
    #pragma unroll
    for (int o = 16; o; o >>= 1) v += __shfl_xor_sync(0xffffffffu, v, o);
    return v;
}

// ---------------- mask zeroing ----------------
__global__ void zeroMaskK(){
    if (threadIdx.x < 4) g_mask[threadIdx.x] = 0u;
}

// ---------------- stage state + violation mask ----------------
__global__ void stageAK(const float* __restrict__ obs, int stage){
    int e = blockIdx.x*blockDim.x + threadIdx.x;
    unsigned bits = 0u;
    if (e < BATCH){
        #pragma unroll
        for (int i = 0; i < 6; i++){
            float q  = obs[e*12 + i];
            float qd = obs[e*12 + 6 + i];
            float qs, qds;
            if (stage == 0){
                qs = q; qds = qd;
            } else if (stage == 1){
                float k1 = g_kqd[0][e*6+i];
                qs  = q + 0.5f*DTc*qd;
                qds = qd + 0.5f*DTc*k1;
            } else if (stage == 2){
                float k1 = g_kqd[0][e*6+i];
                float k2 = g_kqd[1][e*6+i];
                float k2q = qd + 0.5f*DTc*k1;
                qs  = q + 0.5f*DTc*k2q;
                qds = qd + 0.5f*DTc*k2;
            } else {
                float k2 = g_kqd[1][e*6+i];
                float k3 = g_kqd[2][e*6+i];
                float k3q = qd + 0.5f*DTc*k2;
                qs  = q + DTc*k3q;
                qds = qd + DTc*k3;
            }
            g_qs[e*6+i]  = qs;
            g_qds[e*6+i] = qds;
            float lo = c_LOWER[i] + 0.1f;
            float up = c_UPPER[i] - 0.1f;
            if (qs <= lo || qs >= up) bits |= (1u << i);
        }
    }
    if (bits) atomicOr(&g_mask[stage], bits);
}

// ---------------- heavy accel kernel ----------------
__global__ void __launch_bounds__(TPB, 1) stageBK(
    const float* __restrict__ W1L, const float* __restrict__ b1L,
    const float* __restrict__ W2L, const float* __restrict__ b2L,
    const float* __restrict__ W3L, const float* __restrict__ b3L,
    const float* __restrict__ W1V, const float* __restrict__ b1V,
    const float* __restrict__ W2V, const float* __restrict__ b2V,
    const float* __restrict__ W3V, const float* __restrict__ action,
    const float* __restrict__ obs, float* __restrict__ out,
    int stage)
{
    extern __shared__ float s[];
    const int tid = threadIdx.x;

    // stage weights (transposed to in-major) into shared
    for (int i = tid; i < 12*H; i += TPB) s[OFF_S1L + (i%12)*H + i/12] = W1L[i];
    for (int i = tid; i < H*H;  i += TPB) s[OFF_S2L + (i%H)*H + i/H]  = W2L[i];
    for (int i = tid; i < 21*H; i += TPB) s[OFF_S3L + (i%H)*21 + i/H] = W3L[i];
    for (int i = tid; i < 12*H; i += TPB) s[OFF_S1V + (i%12)*H + i/12] = W1V[i];
    for (int i = tid; i < H*H;  i += TPB) s[OFF_S2V + (i%H)*H + i/H]  = W2V[i];
    for (int i = tid; i < H; i += TPB){
        s[OFF_B1L+i]=b1L[i]; s[OFF_B2L+i]=b2L[i];
        s[OFF_B1V+i]=b1V[i]; s[OFF_B2V+i]=b2V[i];
        s[OFF_W3V+i]=W3V[i];
    }
    for (int i = tid; i < 21; i += TPB) s[OFF_B3L+i]=b3L[i];
    __syncthreads();

    const unsigned mask = g_mask[stage];
    const int wid = tid >> 5, lane = tid & 31;
    float* scr   = s + WTOT + wid*SCR;
    float* vecs  = scr;
    float* ydy   = scr + 896;
    float* dmj   = scr + 1043;
    float* psm   = scr + 1169;
    float* gsm   = scr + 1190;
    float* rhssm = scr + 1196;
    float* qsh   = scr + 1202;
    float* qdsh  = scr + 1208;
    float* tcsm  = scr + 1214;
    float* tssm  = scr + 1220;
    const int o0 = lane*4;
    float* kout = g_kqd[stage];

    for (int e = blockIdx.x*WARPS + wid; e < BATCH; e += gridDim.x*WARPS){
        if (lane < 6){
            float qv  = g_qs[e*6+lane];
            float qdv = g_qds[e*6+lane];
            qsh[lane]  = qv;
            qdsh[lane] = qdv;
            float sn, cs;
            __sincosf(qv, &sn, &cs);
            tcsm[lane] = cs;
            tssm[lane] = sn;
        }
        __syncwarp();
        float tc[6], tsn[6], qdr[6];
        #pragma unroll
        for (int i = 0; i < 6; i++){ tc[i]=tcsm[i]; tsn[i]=tssm[i]; qdr[i]=qdsh[i]; }

        // ==================== L network ====================
        // ---- layer 1: value + 6 tangents (pair-interleaved layout)
        {
            float zz[4];
            #pragma unroll
            for (int m=0;m<4;m++) zz[m] = s[OFF_B1L+o0+m];
            #pragma unroll
            for (int k=0;k<12;k++){
                float tk = (k&1) ? tsn[k>>1] : tc[k>>1];
                float4 w = *(const float4*)&s[OFF_S1L + k*H + o0];
                zz[0]+=w.x*tk; zz[1]+=w.y*tk; zz[2]+=w.z*tk; zz[3]+=w.w*tk;
            }
            float s1[4];
            #pragma unroll
            for (int m=0;m<4;m++){
                float spv, sgv; spsig(zz[m], spv, sgv);
                vecs[o0+m] = spv; s1[m] = sgv;
            }
            #pragma unroll
            for (int p=0;p<3;p++){
                int ja = 2*p, jb = 2*p+1;
                float4 waA = *(const float4*)&s[OFF_S1L + (2*ja  )*H + o0];
                float4 wbA = *(const float4*)&s[OFF_S1L + (2*ja+1)*H + o0];
                float4 waB = *(const float4*)&s[OFF_S1L + (2*jb  )*H + o0];
                float4 wbB = *(const float4*)&s[OFF_S1L + (2*jb+1)*H + o0];
                float ca=tc[ja], sa=tsn[ja], cb=tc[jb], sb=tsn[jb];
                float tav[4], tbv[4];
                tav[0]=s1[0]*(wbA.x*ca - waA.x*sa); tbv[0]=s1[0]*(wbB.x*cb - waB.x*sb);
                tav[1]=s1[1]*(wbA.y*ca - waA.y*sa); tbv[1]=s1[1]*(wbB.y*cb - waB.y*sb);
                tav[2]=s1[2]*(wbA.z*ca - waA.z*sa); tbv[2]=s1[2]*(wbB.z*cb - waB.z*sb);
                tav[3]=s1[3]*(wbA.w*ca - waA.w*sa); tbv[3]=s1[3]*(wbB.w*cb - waB.w*sb);
                *(float4*)&vecs[128 + p*256 + 2*o0]     = make_float4(tav[0],tbv[0],tav[1],tbv[1]);
                *(float4*)&vecs[128 + p*256 + 2*o0 + 4] = make_float4(tav[2],tbv[2],tav[3],tbv[3]);
            }
        }
        __syncwarp();

        // ---- layer 2: value scalar + 3 tangent-pair FFMA2 accumulators
        {
            float a0[4];
            #pragma unroll
            for (int m=0;m<4;m++) a0[m] = s[OFF_B2L+o0+m];
            ull accp[3][4];
            #pragma unroll
            for (int p=0;p<3;p++){
                #pragma unroll
                for (int m=0;m<4;m++) accp[p][m]=0ull;
            }
            for (int k=0;k<H;k+=4){
                float4 hval = *(const float4*)&vecs[k];
                ulonglong2 hA[3], hB[3];
                #pragma unroll
                for (int p=0;p<3;p++){
                    hA[p] = *(const ulonglong2*)&vecs[128 + p*256 + 2*k];
                    hB[p] = *(const ulonglong2*)&vecs[128 + p*256 + 2*k + 4];
                }
                #pragma unroll
                for (int kk=0;kk<4;kk++){
                    float4 w = *(const float4*)&s[OFF_S2L + (k+kk)*H + o0];
                    float hs = (&hval.x)[kk];
                    a0[0] += w.x*hs; a0[1] += w.y*hs; a0[2] += w.z*hs; a0[3] += w.w*hs;
                    ull hp0 = (kk==0)? hA[0].x : (kk==1)? hA[0].y : (kk==2)? hB[0].x : hB[0].y;
                    ull hp1 = (kk==0)? hA[1].x : (kk==1)? hA[1].y : (kk==2)? hB[1].x : hB[1].y;
                    ull hp2 = (kk==0)? hA[2].x : (kk==1)? hA[2].y : (kk==2)? hB[2].x : hB[2].y;
                    #pragma unroll
                    for (int m=0;m<4;m++){
                        float wm = (&w.x)[m];
                        ull wd = pk2(wm, wm);
                        accp[0][m] = ffma2(wd, hp0, accp[0][m]);
                        accp[1][m] = ffma2(wd, hp1, accp[1][m]);
                        accp[2][m] = ffma2(wd, hp2, accp[2][m]);
                    }
                }
            }
            __syncwarp();
            float s2[4];
            #pragma unroll
            for (int m=0;m<4;m++){
                float spv, sgv; spsig(a0[m], spv, sgv);
                vecs[o0+m] = spv; s2[m] = sgv;
            }
            #pragma unroll
            for (int p=0;p<3;p++){
                float tav[4], tbv[4];
                #pragma unroll
                for (int m=0;m<4;m++){
                    float xa, xb; upk2(accp[p][m], xa, xb);
                    tav[m] = s2[m]*xa; tbv[m] = s2[m]*xb;
                }
                *(float4*)&vecs[128 + p*256 + 2*o0]     = make_float4(tav[0],tbv[0],tav[1],tbv[1]);
                *(float4*)&vecs[128 + p*256 + 2*o0 + 4] = make_float4(tav[2],tbv[2],tav[3],tbv[3]);
            }
        }
        __syncwarp();

        // ---- layer 3 (21 outputs), FFMA2-packed tangent pairs
        if (lane < 21){
            float f0 = s[OFF_B3L+lane];
            ull fp[3];
            fp[0]=0ull; fp[1]=0ull; fp[2]=0ull;
            for (int k=0;k<H;k+=4){
                float w0 = s[OFF_S3L+(k+0)*21+lane];
                float w1 = s[OFF_S3L+(k+1)*21+lane];
                float w2 = s[OFF_S3L+(k+2)*21+lane];
                float w3 = s[OFF_S3L+(k+3)*21+lane];
                float4 h4 = *(const float4*)&vecs[k];
                f0 += w0*h4.x + w1*h4.y + w2*h4.z + w3*h4.w;
                ull wd0 = pk2(w0,w0), wd1 = pk2(w1,w1);
                ull wd2 = pk2(w2,w2), wd3 = pk2(w3,w3);
                #pragma unroll
                for (int p=0;p<3;p++){
                    ulonglong2 G0 = *(const ulonglong2*)&vecs[128 + p*256 + 2*k];
                    ulonglong2 G1 = *(const ulonglong2*)&vecs[128 + p*256 + 2*k + 4];
                    fp[p] = ffma2(wd0, G0.x, fp[p]);
                    fp[p] = ffma2(wd1, G0.y, fp[p]);
                    fp[p] = ffma2(wd2, G1.x, fp[p]);
                    fp[p] = ffma2(wd3, G1.y, fp[p]);
                }
            }
            float spv, s3; spsig(f0, spv, s3);
            ydy[lane] = spv;
            #pragma unroll
            for (int p=0;p<3;p++){
                float xa, xb; upk2(fp[p], xa, xb);
                ydy[(1+2*p)*21+lane] = s3*xa;
                ydy[(2+2*p)*21+lane] = s3*xb;
            }
        }
        __syncwarp();

        // ==================== V network (forward-mode gradient) ====================
        // ---- layer 1 (pair layout, overwrite vecs)
        {
            float zz[4];
            #pragma unroll
            for (int m=0;m<4;m++) zz[m] = s[OFF_B1V+o0+m];
            #pragma unroll
            for (int k=0;k<12;k++){
                float tk = (k&1) ? tsn[k>>1] : tc[k>>1];
                float4 w = *(const float4*)&s[OFF_S1V + k*H + o0];
                zz[0]+=w.x*tk; zz[1]+=w.y*tk; zz[2]+=w.z*tk; zz[3]+=w.w*tk;
            }
            float s1[4];
            #pragma unroll
            for (int m=0;m<4;m++){
                float spv, sgv; spsig(zz[m], spv, sgv);
                vecs[o0+m] = spv; s1[m] = sgv;
            }
            #pragma unroll
            for (int p=0;p<3;p++){
                int ja = 2*p, jb = 2*p+1;
                float4 waA = *(const float4*)&s[OFF_S1V + (2*ja  )*H + o0];
                float4 wbA = *(const float4*)&s[OFF_S1V + (2*ja+1)*H + o0];
                float4 waB = *(const float4*)&s[OFF_S1V + (2*jb  )*H + o0];
                float4 wbB = *(const float4*)&s[OFF_S1V + (2*jb+1)*H + o0];
                float ca=tc[ja], sa=tsn[ja], cb=tc[jb], sb=tsn[jb];
                float tav[4], tbv[4];
                tav[0]=s1[0]*(wbA.x*ca - waA.x*sa); tbv[0]=s1[0]*(wbB.x*cb - waB.x*sb);
                tav[1]=s1[1]*(wbA.y*ca - waA.y*sa); tbv[1]=s1[1]*(wbB.y*cb - waB.y*sb);
                tav[2]=s1[2]*(wbA.z*ca - waA.z*sa); tbv[2]=s1[2]*(wbB.z*cb - waB.z*sb);
                tav[3]=s1[3]*(wbA.w*ca - waA.w*sa); tbv[3]=s1[3]*(wbB.w*cb - waB.w*sb);
                *(float4*)&vecs[128 + p*256 + 2*o0]     = make_float4(tav[0],tbv[0],tav[1],tbv[1]);
                *(float4*)&vecs[128 + p*256 + 2*o0 + 4] = make_float4(tav[2],tbv[2],tav[3],tbv[3]);
            }
        }
        __syncwarp();

        // ---- layer 2 + gravity
        {
            float a0[4];
            #pragma unroll
            for (int m=0;m<4;m++) a0[m] = s[OFF_B2V+o0+m];
            ull accp[3][4];
            #pragma unroll
            for (int p=0;p<3;p++){
                #pragma unroll
                for (int m=0;m<4;m++) accp[p][m]=0ull;
            }
            for (int k=0;k<H;k+=4){
                float4 hval = *(const float4*)&vecs[k];
                ulonglong2 hA[3], hB[3];
                #pragma unroll
                for (int p=0;p<3;p++){
                    hA[p] = *(const ulonglong2*)&vecs[128 + p*256 + 2*k];
                    hB[p] = *(const ulonglong2*)&vecs[128 + p*256 + 2*k + 4];
                }
                #pragma unroll
                for (int kk=0;kk<4;kk++){
                    float4 w = *(const float4*)&s[OFF_S2V + (k+kk)*H + o0];
                    float hs = (&hval.x)[kk];
                    a0[0] += w.x*hs; a0[1] += w.y*hs; a0[2] += w.z*hs; a0[3] += w.w*hs;
                    ull hp0 = (kk==0)? hA[0].x : (kk==1)? hA[0].y : (kk==2)? hB[0].x : hB[0].y;
                    ull hp1 = (kk==0)? hA[1].x : (kk==1)? hA[1].y : (kk==2)? hB[1].x : hB[1].y;
                    ull hp2 = (kk==0)? hA[2].x : (kk==1)? hA[2].y : (kk==2)? hB[2].x : hB[2].y;
                    #pragma unroll
                    for (int m=0;m<4;m++){
                        float wm = (&w.x)[m];
                        ull wd = pk2(wm, wm);
                        accp[0][m] = ffma2(wd, hp0, accp[0][m]);
                        accp[1][m] = ffma2(wd, hp1, accp[1][m]);
                        accp[2][m] = ffma2(wd, hp2, accp[2][m]);
                    }
                }
            }
            float pj[6];
            #pragma unroll
            for (int j=0;j<6;j++) pj[j]=0.f;
            #pragma unroll
            for (int m=0;m<4;m++){
                float wv = s[OFF_W3V+o0+m] * sig_f(a0[m]);
                #pragma unroll
                for (int p=0;p<3;p++){
                    float xa, xb; upk2(accp[p][m], xa, xb);
                    pj[2*p]   += wv*xa;
                    pj[2*p+1] += wv*xb;
                }
            }
            #pragma unroll
            for (int j=0;j<6;j++){
                float g = wsum(pj[j]);
                if (lane == 0) gsm[j] = g;
            }
        }
        __syncwarp();

        // ---- dM_j lower-tri entries
        for (int t = lane; t < 126; t += 32){
            int j = t/21, u = t%21;
            int a = c_TI[u], b = c_TJ[u];
            int ta = a*(a+1)/2, tb = b*(b+1)/2;
            const float* Lr = ydy;
            const float* Dr = ydy + (j+1)*21;
            float sacc = 0.f;
            for (int m = 0; m <= b; m++)
                sacc += Dr[ta+m]*Lr[tb+m] + Lr[ta+m]*Dr[tb+m];
            dmj[t] = sacc;
        }
        __syncwarp();

        // ---- P = sum_j qdot_j dM_j
        if (lane < 21){
            float p = 0.f;
            #pragma unroll
            for (int j=0;j<6;j++) p += qdr[j]*dmj[j*21+lane];
            psm[lane] = p;
        }
        __syncwarp();

        // ---- c_i, constraints, rhs
        if (lane < 6){
            int i = lane;
            float c1 = 0.f;
            #pragma unroll
            for (int b=0;b<6;b++){
                int idx = (i >= b) ? (i*(i+1)/2 + b) : (b*(b+1)/2 + i);
                c1 += psm[idx]*qdr[b];
            }
            float qf = 0.f;   // 0.5 * qd^T dM_i qd
            for (int u2=0; u2<21; u2++){
                int a = c_TI[u2], b = c_TJ[u2];
                float w = (a==b) ? 0.5f : 1.0f;
                qf += w*dmj[i*21+u2]*qdsh[a]*qdsh[b];
            }
            float ci = c1 - qf;
            float qi = qsh[i];
            float lo = c_LOWER[i] + 0.1f;
            float up = c_UPPER[i] - 0.1f;
            float fi;
            if (mask & (1u << i))
                fi = (qi <= lo) ? c_EFFORT[i] : ((qi >= up) ? -c_EFFORT[i] : 0.0f);
            else
                fi = -5.0f*(__fdividef(1.0f, qi-lo) - __fdividef(1.0f, up-qi));
            float tau = action[e*6+i]*c_EFFORT[i];
            rhssm[i] = tau - ci - gsm[i] - fi;
        }
        __syncwarp();

        // ---- solve (L L^T) x = rhs; stage 3 also does the final RK4 combine
        if (lane == 0){
            float Lm[6][6];
            #pragma unroll
            for (int i=0;i<6;i++){
                #pragma unroll
                for (int jj=0;jj<6;jj++)
                    Lm[i][jj] = (jj<=i) ? ydy[i*(i+1)/2+jj] : 0.f;
            }
            float rinv[6];
            #pragma unroll
            for (int i=0;i<6;i++) rinv[i] = __fdividef(1.0f, Lm[i][i]);
            float wv[6], x[6];
            #pragma unroll
            for (int i=0;i<6;i++){
                float sr = rhssm[i];
                #pragma unroll
                for (int jj=0;jj<6;jj++) if (jj < i) sr -= Lm[i][jj]*wv[jj];
                wv[i] = sr * rinv[i];
            }
            #pragma unroll
            for (int i=5;i>=0;i--){
                float sr = wv[i];
                #pragma unroll
                for (int jj=0;jj<6;jj++) if (jj > i) sr -= Lm[jj][i]*x[jj];
                x[i] = sr * rinv[i];
            }
            if (stage < 3){
                #pragma unroll
                for (int i=0;i<6;i++) kout[e*6+i] = x[i];
            } else {
                // fused final RK4 combine (k4 = x)
                #pragma unroll
                for (int i=0;i<6;i++){
                    float q  = obs[e*12 + i];
                    float qd = obs[e*12 + 6 + i];
                    float k1 = g_kqd[0][e*6+i];
                    float k2 = g_kqd[1][e*6+i];
                    float k3 = g_kqd[2][e*6+i];
                    float k4 = x[i];
                    float k1q = qd;
                    float k2q = qd + 0.5f*DTc*k1;
                    float k3q = qd + 0.5f*DTc*k2;
                    float k4q = qd + DTc*k3;
                    float qn  = q  + (DTc/6.0f)*(k1q + 2.f*k2q + 2.f*k3q + k4q);
                    float qdn = qd + (DTc/6.0f)*(k1  + 2.f*k2  + 2.f*k3  + k4 );
                    qn = fminf(fmaxf(qn, c_LOWER[i]), c_UPPER[i]);
                    out[e*12 + i]     = qn;
                    out[e*12 + 6 + i] = qdn;
                }
            }
        }
        __syncwarp();
    }
}

extern "C" void kernel_launch(void* const* d_in, const int* in_sizes, int n_in,
                              void* d_out, int out_size)
{
    const float* obs    = (const float*)d_in[0];
    const float* action = (const float*)d_in[1];
    const float* W1L = (const float*)d_in[2];  const float* b1L = (const float*)d_in[3];
    const float* W2L = (const float*)d_in[4];  const float* b2L = (const float*)d_in[5];
    const float* W3L = (const float*)d_in[6];  const float* b3L = (const float*)d_in[7];
    const float* W1V = (const float*)d_in[8];  const float* b1V = (const float*)d_in[9];
    const float* W2V = (const float*)d_in[10]; const float* b2V = (const float*)d_in[11];
    const float* W3V = (const float*)d_in[12];
    float* out = (float*)d_out;

    cudaFuncSetAttribute(stageBK, cudaFuncAttributeMaxDynamicSharedMemorySize, SMEM_BYTES);

    zeroMaskK<<<1, 32>>>();
    for (int st = 0; st < 4; st++){
        stageAK<<<BATCH/256, 256>>>(obs, st);
        stageBK<<<NBLK, TPB, SMEM_BYTES>>>(W1L,b1L,W2L,b2L,W3L,b3L,
                                           W1V,b1V,W2V,b2V,W3V, action,
                                           obs, out, st);
    }
}

// round 14
// speedup vs baseline: 1.0952x; 1.0792x over previous
#include <cuda_runtime.h>
#include <math.h>

#define BATCH 16384
#define B6 (BATCH*6)
#define H 128
#define DTc 0.01f
#define WARPS 14
#define TPB (WARPS*32)
#define NBLK 152

// ---- shared-memory weight layout (float offsets) ----
#define OFF_S1L 0        // [12][128]  W1L^T
#define OFF_S2L 1536     // [128][128] W2L^T (in-major)
#define OFF_S3L 17920    // [128][21]  W3L^T
#define OFF_B1L 20608
#define OFF_B2L 20736
#define OFF_B3L 20864    // 24 slots (21 used)
#define OFF_S1V 20888    // [12][128]  W1V^T (in-major)
#define OFF_S2VO 22424   // [128][129] W2V original [m][k], odd stride 129
#define OFF_W3V 38936    // [128]
#define OFF_B1V 39064
#define OFF_B2V 39192
#define WTOT    39320
#define SCR     1228     // per-warp scratch floats
#define SMEM_FLOATS (WTOT + WARPS*SCR)
#define SMEM_BYTES  (SMEM_FLOATS*4)

// per-warp scratch sublayout:
// vecs  [896]  @0    : L-net value[128] + 3 pair-rows[256]; V-net h[128], sv1[128], a2s[128]
// ydy   [147]  @896
// dmj   [126]  @1043
// psm   [21]   @1169
// gsm   [6]    @1190
// rhssm [6]    @1196
// qsh   [6]    @1202
// qdsh  [6]    @1208
// tcsm  [6]    @1214
// tssm  [6]    @1220

typedef unsigned long long ull;

__device__ float g_qs[B6];
__device__ float g_qds[B6];
__device__ float g_kqd[4][B6];
__device__ unsigned g_mask[4];

__constant__ float c_LOWER[6]  = {-6.28f,-6.28f,-3.14f,-6.28f,-6.28f,-6.28f};
__constant__ float c_UPPER[6]  = { 6.28f, 6.28f, 3.14f, 6.28f, 6.28f, 6.28f};
__constant__ float c_EFFORT[6] = {150.f,150.f,150.f,28.f,28.f,28.f};
__constant__ int   c_TI[21] = {0,1,1,2,2,2,3,3,3,3,4,4,4,4,4,5,5,5,5,5,5};
__constant__ int   c_TJ[21] = {0,0,1,0,1,2,0,1,2,3,0,1,2,3,4,0,1,2,3,4,5};

// ---- packed fp32x2 helpers ----
__device__ __forceinline__ ull pk2(float a, float b){
    ull r; asm("mov.b64 %0, {%1, %2};" : "=l"(r) : "f"(a), "f"(b)); return r;
}
__device__ __forceinline__ void upk2(ull v, float& a, float& b){
    asm("mov.b64 {%0, %1}, %2;" : "=f"(a), "=f"(b) : "l"(v));
}
__device__ __forceinline__ ull ffma2(ull a, ull b, ull c){
    ull d; asm("fma.rn.f32x2 %0, %1, %2, %3;" : "=l"(d) : "l"(a), "l"(b), "l"(c)); return d;
}

// fast softplus + sigmoid sharing one exp
__device__ __forceinline__ void spsig(float x, float& sp, float& sg){
    float e = __expf(-fabsf(x));
    float r = __fdividef(1.0f, 1.0f + e);
    sp = fmaxf(x, 0.0f) + __logf(1.0f + e);
    sg = (x >= 0.0f) ? r : (1.0f - r);
}
__device__ __forceinline__ float sig_f(float x){
    float e = __expf(-fabsf(x));
    float r = __fdividef(1.0f, 1.0f + e);
    return (x >= 0.0f) ? r : (1.0f - r);
}
__device__ __forceinline__ float wsum(float v){
    #pragma unroll
    for (int o = 16; o; o >>= 1) v += __shfl_xor_sync(0xffffffffu, v, o);
    return v;
}

// ---------------- mask zeroing ----------------
__global__ void zeroMaskK(){
    if (threadIdx.x < 4) g_mask[threadIdx.x] = 0u;
}

// ---------------- stage state + violation mask ----------------
__global__ void stageAK(const float* __restrict__ obs, int stage){
    int e = blockIdx.x*blockDim.x + threadIdx.x;
    unsigned bits = 0u;
    if (e < BATCH){
        #pragma unroll
        for (int i = 0; i < 6; i++){
            float q  = obs[e*12 + i];
            float qd = obs[e*12 + 6 + i];
            float qs, qds;
            if (stage == 0){
                qs = q; qds = qd;
            } else if (stage == 1){
                float k1 = g_kqd[0][e*6+i];
                qs  = q + 0.5f*DTc*qd;
                qds = qd + 0.5f*DTc*k1;
            } else if (stage == 2){
                float k1 = g_kqd[0][e*6+i];
                float k2 = g_kqd[1][e*6+i];
                float k2q = qd + 0.5f*DTc*k1;
                qs  = q + 0.5f*DTc*k2q;
                qds = qd + 0.5f*DTc*k2;
            } else {
                float k2 = g_kqd[1][e*6+i];
                float k3 = g_kqd[2][e*6+i];
                float k3q = qd + 0.5f*DTc*k2;
                qs  = q + DTc*k3q;
                qds = qd + DTc*k3;
            }
            g_qs[e*6+i]  = qs;
            g_qds[e*6+i] = qds;
            float lo = c_LOWER[i] + 0.1f;
            float up = c_UPPER[i] - 0.1f;
            if (qs <= lo || qs >= up) bits |= (1u << i);
        }
    }
    if (bits) atomicOr(&g_mask[stage], bits);
}

// ---------------- heavy accel kernel ----------------
__global__ void __launch_bounds__(TPB, 1) stageBK(
    const float* __restrict__ W1L, const float* __restrict__ b1L,
    const float* __restrict__ W2L, const float* __restrict__ b2L,
    const float* __restrict__ W3L, const float* __restrict__ b3L,
    const float* __restrict__ W1V, const float* __restrict__ b1V,
    const float* __restrict__ W2V, const float* __restrict__ b2V,
    const float* __restrict__ W3V, const float* __restrict__ action,
    const float* __restrict__ obs, float* __restrict__ out,
    int stage)
{
    extern __shared__ float s[];
    const int tid = threadIdx.x;

    // stage weights into shared
    for (int i = tid; i < 12*H; i += TPB) s[OFF_S1L + (i%12)*H + i/12] = W1L[i];
    for (int i = tid; i < H*H;  i += TPB) s[OFF_S2L + (i%H)*H + i/H]  = W2L[i];
    for (int i = tid; i < 21*H; i += TPB) s[OFF_S3L + (i%H)*21 + i/H] = W3L[i];
    for (int i = tid; i < 12*H; i += TPB) s[OFF_S1V + (i%12)*H + i/12] = W1V[i];
    for (int i = tid; i < H*H;  i += TPB){
        int m = i / H, k = i % H;
        s[OFF_S2VO + m*129 + k] = W2V[i];   // original [out][in], stride 129
    }
    for (int i = tid; i < H; i += TPB){
        s[OFF_B1L+i]=b1L[i]; s[OFF_B2L+i]=b2L[i];
        s[OFF_B1V+i]=b1V[i]; s[OFF_B2V+i]=b2V[i];
        s[OFF_W3V+i]=W3V[i];
    }
    for (int i = tid; i < 21; i += TPB) s[OFF_B3L+i]=b3L[i];
    __syncthreads();

    const unsigned mask = g_mask[stage];
    const int wid = tid >> 5, lane = tid & 31;
    float* scr   = s + WTOT + wid*SCR;
    float* vecs  = scr;
    float* ydy   = scr + 896;
    float* dmj   = scr + 1043;
    float* psm   = scr + 1169;
    float* gsm   = scr + 1190;
    float* rhssm = scr + 1196;
    float* qsh   = scr + 1202;
    float* qdsh  = scr + 1208;
    float* tcsm  = scr + 1214;
    float* tssm  = scr + 1220;
    const int o0 = lane*4;
    float* kout = g_kqd[stage];

    for (int e = blockIdx.x*WARPS + wid; e < BATCH; e += gridDim.x*WARPS){
        if (lane < 6){
            float qv  = g_qs[e*6+lane];
            float qdv = g_qds[e*6+lane];
            qsh[lane]  = qv;
            qdsh[lane] = qdv;
            float sn, cs;
            __sincosf(qv, &sn, &cs);
            tcsm[lane] = cs;
            tssm[lane] = sn;
        }
        __syncwarp();
        float tc[6], tsn[6], qdr[6];
        #pragma unroll
        for (int i = 0; i < 6; i++){ tc[i]=tcsm[i]; tsn[i]=tssm[i]; qdr[i]=qdsh[i]; }

        // ==================== L network ====================
        // ---- layer 1: value + 6 tangents (pair-interleaved layout)
        {
            float zz[4];
            #pragma unroll
            for (int m=0;m<4;m++) zz[m] = s[OFF_B1L+o0+m];
            #pragma unroll
            for (int k=0;k<12;k++){
                float tk = (k&1) ? tsn[k>>1] : tc[k>>1];
                float4 w = *(const float4*)&s[OFF_S1L + k*H + o0];
                zz[0]+=w.x*tk; zz[1]+=w.y*tk; zz[2]+=w.z*tk; zz[3]+=w.w*tk;
            }
            float s1[4];
            #pragma unroll
            for (int m=0;m<4;m++){
                float spv, sgv; spsig(zz[m], spv, sgv);
                vecs[o0+m] = spv; s1[m] = sgv;
            }
            #pragma unroll
            for (int p=0;p<3;p++){
                int ja = 2*p, jb = 2*p+1;
                float4 waA = *(const float4*)&s[OFF_S1L + (2*ja  )*H + o0];
                float4 wbA = *(const float4*)&s[OFF_S1L + (2*ja+1)*H + o0];
                float4 waB = *(const float4*)&s[OFF_S1L + (2*jb  )*H + o0];
                float4 wbB = *(const float4*)&s[OFF_S1L + (2*jb+1)*H + o0];
                float ca=tc[ja], sa=tsn[ja], cb=tc[jb], sb=tsn[jb];
                float tav[4], tbv[4];
                tav[0]=s1[0]*(wbA.x*ca - waA.x*sa); tbv[0]=s1[0]*(wbB.x*cb - waB.x*sb);
                tav[1]=s1[1]*(wbA.y*ca - waA.y*sa); tbv[1]=s1[1]*(wbB.y*cb - waB.y*sb);
                tav[2]=s1[2]*(wbA.z*ca - waA.z*sa); tbv[2]=s1[2]*(wbB.z*cb - waB.z*sb);
                tav[3]=s1[3]*(wbA.w*ca - waA.w*sa); tbv[3]=s1[3]*(wbB.w*cb - waB.w*sb);
                *(float4*)&vecs[128 + p*256 + 2*o0]     = make_float4(tav[0],tbv[0],tav[1],tbv[1]);
                *(float4*)&vecs[128 + p*256 + 2*o0 + 4] = make_float4(tav[2],tbv[2],tav[3],tbv[3]);
            }
        }
        __syncwarp();

        // ---- layer 2: value scalar + 3 tangent-pair FFMA2 accumulators
        {
            float a0[4];
            #pragma unroll
            for (int m=0;m<4;m++) a0[m] = s[OFF_B2L+o0+m];
            ull accp[3][4];
            #pragma unroll
            for (int p=0;p<3;p++){
                #pragma unroll
                for (int m=0;m<4;m++) accp[p][m]=0ull;
            }
            for (int k=0;k<H;k+=4){
                float4 hval = *(const float4*)&vecs[k];
                ulonglong2 hA[3], hB[3];
                #pragma unroll
                for (int p=0;p<3;p++){
                    hA[p] = *(const ulonglong2*)&vecs[128 + p*256 + 2*k];
                    hB[p] = *(const ulonglong2*)&vecs[128 + p*256 + 2*k + 4];
                }
                #pragma unroll
                for (int kk=0;kk<4;kk++){
                    float4 w = *(const float4*)&s[OFF_S2L + (k+kk)*H + o0];
                    float hs = (&hval.x)[kk];
                    a0[0] += w.x*hs; a0[1] += w.y*hs; a0[2] += w.z*hs; a0[3] += w.w*hs;
                    ull hp0 = (kk==0)? hA[0].x : (kk==1)? hA[0].y : (kk==2)? hB[0].x : hB[0].y;
                    ull hp1 = (kk==0)? hA[1].x : (kk==1)? hA[1].y : (kk==2)? hB[1].x : hB[1].y;
                    ull hp2 = (kk==0)? hA[2].x : (kk==1)? hA[2].y : (kk==2)? hB[2].x : hB[2].y;
                    #pragma unroll
                    for (int m=0;m<4;m++){
                        float wm = (&w.x)[m];
                        ull wd = pk2(wm, wm);
                        accp[0][m] = ffma2(wd, hp0, accp[0][m]);
                        accp[1][m] = ffma2(wd, hp1, accp[1][m]);
                        accp[2][m] = ffma2(wd, hp2, accp[2][m]);
                    }
                }
            }
            __syncwarp();
            float s2[4];
            #pragma unroll
            for (int m=0;m<4;m++){
                float spv, sgv; spsig(a0[m], spv, sgv);
                vecs[o0+m] = spv; s2[m] = sgv;
            }
            #pragma unroll
            for (int p=0;p<3;p++){
                float tav[4], tbv[4];
                #pragma unroll
                for (int m=0;m<4;m++){
                    float xa, xb; upk2(accp[p][m], xa, xb);
                    tav[m] = s2[m]*xa; tbv[m] = s2[m]*xb;
                }
                *(float4*)&vecs[128 + p*256 + 2*o0]     = make_float4(tav[0],tbv[0],tav[1],tbv[1]);
                *(float4*)&vecs[128 + p*256 + 2*o0 + 4] = make_float4(tav[2],tbv[2],tav[3],tbv[3]);
            }
        }
        __syncwarp();

        // ---- layer 3 (21 outputs), FFMA2-packed tangent pairs
        if (lane < 21){
            float f0 = s[OFF_B3L+lane];
            ull fp[3];
            fp[0]=0ull; fp[1]=0ull; fp[2]=0ull;
            for (int k=0;k<H;k+=4){
                float w0 = s[OFF_S3L+(k+0)*21+lane];
                float w1 = s[OFF_S3L+(k+1)*21+lane];
                float w2 = s[OFF_S3L+(k+2)*21+lane];
                float w3 = s[OFF_S3L+(k+3)*21+lane];
                float4 h4 = *(const float4*)&vecs[k];
                f0 += w0*h4.x + w1*h4.y + w2*h4.z + w3*h4.w;
                ull wd0 = pk2(w0,w0), wd1 = pk2(w1,w1);
                ull wd2 = pk2(w2,w2), wd3 = pk2(w3,w3);
                #pragma unroll
                for (int p=0;p<3;p++){
                    ulonglong2 G0 = *(const ulonglong2*)&vecs[128 + p*256 + 2*k];
                    ulonglong2 G1 = *(const ulonglong2*)&vecs[128 + p*256 + 2*k + 4];
                    fp[p] = ffma2(wd0, G0.x, fp[p]);
                    fp[p] = ffma2(wd1, G0.y, fp[p]);
                    fp[p] = ffma2(wd2, G1.x, fp[p]);
                    fp[p] = ffma2(wd3, G1.y, fp[p]);
                }
            }
            float spv, s3; spsig(f0, spv, s3);
            ydy[lane] = spv;
            #pragma unroll
            for (int p=0;p<3;p++){
                float xa, xb; upk2(fp[p], xa, xb);
                ydy[(1+2*p)*21+lane] = s3*xa;
                ydy[(2+2*p)*21+lane] = s3*xb;
            }
        }
        __syncwarp();

        // ==================== V network (REVERSE-mode gradient) ====================
        // ---- layer 1: value only; store h1 -> vecs[0..128), sv1 -> vecs[128..256)
        {
            float zz[4];
            #pragma unroll
            for (int m=0;m<4;m++) zz[m] = s[OFF_B1V+o0+m];
            #pragma unroll
            for (int k=0;k<12;k++){
                float tk = (k&1) ? tsn[k>>1] : tc[k>>1];
                float4 w = *(const float4*)&s[OFF_S1V + k*H + o0];
                zz[0]+=w.x*tk; zz[1]+=w.y*tk; zz[2]+=w.z*tk; zz[3]+=w.w*tk;
            }
            #pragma unroll
            for (int m=0;m<4;m++){
                float spv, sgv; spsig(zz[m], spv, sgv);
                vecs[o0+m]       = spv;
                vecs[128+o0+m]   = sgv;
            }
        }
        __syncwarp();

        // ---- layer 2 forward (value only): lane owns m = lane+32t, conflict-free scalar rows
        {
            float a0[4];
            #pragma unroll
            for (int t=0;t<4;t++) a0[t] = s[OFF_B2V + lane + 32*t];
            for (int k=0;k<H;k+=4){
                float h0=vecs[k], h1v=vecs[k+1], h2=vecs[k+2], h3=vecs[k+3];
                #pragma unroll
                for (int t=0;t<4;t++){
                    const float* row = &s[OFF_S2VO + (lane+32*t)*129];
                    a0[t] += row[k]*h0 + row[k+1]*h1v + row[k+2]*h2 + row[k+3]*h3;
                }
            }
            // a2s[m] = W3V[m] * sigmoid(z2[m])  -> vecs[256..384)
            #pragma unroll
            for (int t=0;t<4;t++)
                vecs[256 + lane + 32*t] = s[OFF_W3V + lane + 32*t] * sig_f(a0[t]);
        }
        __syncwarp();

        // ---- layer 2 backward: gb[k] = sum_m W[m][k]*a2s[m]; lane owns k = lane+32t
        float a1r[4];
        {
            float gb[4];
            #pragma unroll
            for (int t=0;t<4;t++) gb[t]=0.f;
            for (int m=0;m<H;m+=4){
                float b0=vecs[256+m], b1v=vecs[256+m+1], b2=vecs[256+m+2], b3=vecs[256+m+3];
                #pragma unroll
                for (int t=0;t<4;t++){
                    int k = lane + 32*t;
                    gb[t] += s[OFF_S2VO + (m+0)*129 + k]*b0
                           + s[OFF_S2VO + (m+1)*129 + k]*b1v
                           + s[OFF_S2VO + (m+2)*129 + k]*b2
                           + s[OFF_S2VO + (m+3)*129 + k]*b3;
                }
            }
            #pragma unroll
            for (int t=0;t<4;t++) a1r[t] = gb[t]*vecs[128 + lane + 32*t];
        }

        // ---- gravity: g_j = sum_k a1[k]*(W1V[k][2j+1]c_j - W1V[k][2j]s_j)
        {
            #pragma unroll
            for (int j=0;j<6;j++){
                float cj=tc[j], sj=tsn[j];
                float p = 0.f;
                #pragma unroll
                for (int t=0;t<4;t++){
                    int k = lane + 32*t;
                    p += a1r[t]*(s[OFF_S1V + (2*j+1)*H + k]*cj - s[OFF_S1V + (2*j)*H + k]*sj);
                }
                float g = wsum(p);
                if (lane == 0) gsm[j] = g;
            }
        }
        __syncwarp();

        // ---- dM_j lower-tri entries
        for (int t = lane; t < 126; t += 32){
            int j = t/21, u = t%21;
            int a = c_TI[u], b = c_TJ[u];
            int ta = a*(a+1)/2, tb = b*(b+1)/2;
            const float* Lr = ydy;
            const float* Dr = ydy + (j+1)*21;
            float sacc = 0.f;
            for (int m = 0; m <= b; m++)
                sacc += Dr[ta+m]*Lr[tb+m] + Lr[ta+m]*Dr[tb+m];
            dmj[t] = sacc;
        }
        __syncwarp();

        // ---- P = sum_j qdot_j dM_j
        if (lane < 21){
            float p = 0.f;
            #pragma unroll
            for (int j=0;j<6;j++) p += qdr[j]*dmj[j*21+lane];
            psm[lane] = p;
        }
        __syncwarp();

        // ---- c_i, constraints, rhs
        if (lane < 6){
            int i = lane;
            float c1 = 0.f;
            #pragma unroll
            for (int b=0;b<6;b++){
                int idx = (i >= b) ? (i*(i+1)/2 + b) : (b*(b+1)/2 + i);
                c1 += psm[idx]*qdr[b];
            }
            float qf = 0.f;   // 0.5 * qd^T dM_i qd
            for (int u2=0; u2<21; u2++){
                int a = c_TI[u2], b = c_TJ[u2];
                float w = (a==b) ? 0.5f : 1.0f;
                qf += w*dmj[i*21+u2]*qdsh[a]*qdsh[b];
            }
            float ci = c1 - qf;
            float qi = qsh[i];
            float lo = c_LOWER[i] + 0.1f;
            float up = c_UPPER[i] - 0.1f;
            float fi;
            if (mask & (1u << i))
                fi = (qi <= lo) ? c_EFFORT[i] : ((qi >= up) ? -c_EFFORT[i] : 0.0f);
            else
                fi = -5.0f*(__fdividef(1.0f, qi-lo) - __fdividef(1.0f, up-qi));
            float tau = action[e*6+i]*c_EFFORT[i];
            rhssm[i] = tau - ci - gsm[i] - fi;
        }
        __syncwarp();

        // ---- solve (L L^T) x = rhs; stage 3 also does the final RK4 combine
        if (lane == 0){
            float Lm[6][6];
            #pragma unroll
            for (int i=0;i<6;i++){
                #pragma unroll
                for (int jj=0;jj<6;jj++)
                    Lm[i][jj] = (jj<=i) ? ydy[i*(i+1)/2+jj] : 0.f;
            }
            float rinv[6];
            #pragma unroll
            for (int i=0;i<6;i++) rinv[i] = __fdividef(1.0f, Lm[i][i]);
            float wv[6], x[6];
            #pragma unroll
            for (int i=0;i<6;i++){
                float sr = rhssm[i];
                #pragma unroll
                for (int jj=0;jj<6;jj++) if (jj < i) sr -= Lm[i][jj]*wv[jj];
                wv[i] = sr * rinv[i];
            }
            #pragma unroll
            for (int i=5;i>=0;i--){
                float sr = wv[i];
                #pragma unroll
                for (int jj=0;jj<6;jj++) if (jj > i) sr -= Lm[jj][i]*x[jj];
                x[i] = sr * rinv[i];
            }
            if (stage < 3){
                #pragma unroll
                for (int i=0;i<6;i++) kout[e*6+i] = x[i];
            } else {
                // fused final RK4 combine (k4 = x)
                #pragma unroll
                for (int i=0;i<6;i++){
                    float q  = obs[e*12 + i];
                    float qd = obs[e*12 + 6 + i];
                    float k1 = g_kqd[0][e*6+i];
                    float k2 = g_kqd[1][e*6+i];
                    float k3 = g_kqd[2][e*6+i];
                    float k4 = x[i];
                    float k1q = qd;
                    float k2q = qd + 0.5f*DTc*k1;
                    float k3q = qd + 0.5f*DTc*k2;
                    float k4q = qd + DTc*k3;
                    float qn  = q  + (DTc/6.0f)*(k1q + 2.f*k2q + 2.f*k3q + k4q);
                    float qdn = qd + (DTc/6.0f)*(k1  + 2.f*k2  + 2.f*k3  + k4 );
                    qn = fminf(fmaxf(qn, c_LOWER[i]), c_UPPER[i]);
                    out[e*12 + i]     = qn;
                    out[e*12 + 6 + i] = qdn;
                }
            }
        }
        __syncwarp();
    }
}

extern "C" void kernel_launch(void* const* d_in, const int* in_sizes, int n_in,
                              void* d_out, int out_size)
{
    const float* obs    = (const float*)d_in[0];
    const float* action = (const float*)d_in[1];
    const float* W1L = (const float*)d_in[2];  const float* b1L = (const float*)d_in[3];
    const float* W2L = (const float*)d_in[4];  const float* b2L = (const float*)d_in[5];
    const float* W3L = (const float*)d_in[6];  const float* b3L = (const float*)d_in[7];
    const float* W1V = (const float*)d_in[8];  const float* b1V = (const float*)d_in[9];
    const float* W2V = (const float*)d_in[10]; const float* b2V = (const float*)d_in[11];
    const float* W3V = (const float*)d_in[12];
    float* out = (float*)d_out;

    cudaFuncSetAttribute(stageBK, cudaFuncAttributeMaxDynamicSharedMemorySize, SMEM_BYTES);

    zeroMaskK<<<1, 32>>>();
    for (int st = 0; st < 4; st++){
        stageAK<<<BATCH/256, 256>>>(obs, st);
        stageBK<<<NBLK, TPB, SMEM_BYTES>>>(W1L,b1L,W2L,b2L,W3L,b3L,
                                           W1V,b1V,W2V,b2V,W3V, action,
                                           obs, out, st);
    }
}

// round 15
// speedup vs baseline: 1.1147x; 1.0178x over previous
#include <cuda_runtime.h>
#include <math.h>

#define BATCH 16384
#define B6 (BATCH*6)
#define H 128
#define DTc 0.01f
#define WARPS 14
#define TPB (WARPS*32)
#define NBLK 152

// ---- shared-memory weight layout (float offsets) ----
#define OFF_S1L 0        // [12][128]  W1L^T
#define OFF_S2L 1536     // [128][128] W2L^T (in-major)
#define OFF_S3L 17920    // [128][21]  W3L^T
#define OFF_B1L 20608
#define OFF_B2L 20736
#define OFF_B3L 20864    // 24 slots (21 used)
#define OFF_S1V 20888    // [12][128]  W1V^T (in-major)
#define OFF_S2VO 22424   // [128][130] W2V original [m][k], EVEN stride 130
#define OFF_W3V 39064    // [128]
#define OFF_B1V 39192
#define OFF_B2V 39320
#define WTOT    39448
#define SCR     1228     // per-warp scratch floats
#define SMEM_FLOATS (WTOT + WARPS*SCR)
#define SMEM_BYTES  (SMEM_FLOATS*4)

typedef unsigned long long ull;

__device__ float g_qs[B6];
__device__ float g_qds[B6];
__device__ float g_kqd[4][B6];
__device__ unsigned g_mask[4];

__constant__ float c_LOWER[6]  = {-6.28f,-6.28f,-3.14f,-6.28f,-6.28f,-6.28f};
__constant__ float c_UPPER[6]  = { 6.28f, 6.28f, 3.14f, 6.28f, 6.28f, 6.28f};
__constant__ float c_EFFORT[6] = {150.f,150.f,150.f,28.f,28.f,28.f};
__constant__ int   c_TI[21] = {0,1,1,2,2,2,3,3,3,3,4,4,4,4,4,5,5,5,5,5,5};
__constant__ int   c_TJ[21] = {0,0,1,0,1,2,0,1,2,3,0,1,2,3,4,0,1,2,3,4,5};

// ---- packed fp32x2 helpers ----
__device__ __forceinline__ ull pk2(float a, float b){
    ull r; asm("mov.b64 %0, {%1, %2};" : "=l"(r) : "f"(a), "f"(b)); return r;
}
__device__ __forceinline__ void upk2(ull v, float& a, float& b){
    asm("mov.b64 {%0, %1}, %2;" : "=f"(a), "=f"(b) : "l"(v));
}
__device__ __forceinline__ ull ffma2(ull a, ull b, ull c){
    ull d; asm("fma.rn.f32x2 %0, %1, %2, %3;" : "=l"(d) : "l"(a), "l"(b), "l"(c)); return d;
}
__device__ __forceinline__ float hsum2(ull v){
    float a, b; upk2(v, a, b); return a + b;
}

// fast softplus + sigmoid sharing one exp
__device__ __forceinline__ void spsig(float x, float& sp, float& sg){
    float e = __expf(-fabsf(x));
    float r = __fdividef(1.0f, 1.0f + e);
    sp = fmaxf(x, 0.0f) + __logf(1.0f + e);
    sg = (x >= 0.0f) ? r : (1.0f - r);
}
__device__ __forceinline__ float sig_f(float x){
    float e = __expf(-fabsf(x));
    float r = __fdividef(1.0f, 1.0f + e);
    return (x >= 0.0f) ? r : (1.0f - r);
}
__device__ __forceinline__ float wsum(float v){
    #pragma unroll
    for (int o = 16; o; o >>= 1) v += __shfl_xor_sync(0xffffffffu, v, o);
    return v;
}

// ---------------- mask zeroing ----------------
__global__ void zeroMaskK(){
    if (threadIdx.x < 4) g_mask[threadIdx.x] = 0u;
}

// ---------------- stage state + violation mask ----------------
__global__ void stageAK(const float* __restrict__ obs, int stage){
    int e = blockIdx.x*blockDim.x + threadIdx.x;
    unsigned bits = 0u;
    if (e < BATCH){
        #pragma unroll
        for (int i = 0; i < 6; i++){
            float q  = obs[e*12 + i];
            float qd = obs[e*12 + 6 + i];
            float qs, qds;
            if (stage == 0){
                qs = q; qds = qd;
            } else if (stage == 1){
                float k1 = g_kqd[0][e*6+i];
                qs  = q + 0.5f*DTc*qd;
                qds = qd + 0.5f*DTc*k1;
            } else if (stage == 2){
                float k1 = g_kqd[0][e*6+i];
                float k2 = g_kqd[1][e*6+i];
                float k2q = qd + 0.5f*DTc*k1;
                qs  = q + 0.5f*DTc*k2q;
                qds = qd + 0.5f*DTc*k2;
            } else {
                float k2 = g_kqd[1][e*6+i];
                float k3 = g_kqd[2][e*6+i];
                float k3q = qd + 0.5f*DTc*k2;
                qs  = q + DTc*k3q;
                qds = qd + DTc*k3;
            }
            g_qs[e*6+i]  = qs;
            g_qds[e*6+i] = qds;
            float lo = c_LOWER[i] + 0.1f;
            float up = c_UPPER[i] - 0.1f;
            if (qs <= lo || qs >= up) bits |= (1u << i);
        }
    }
    if (bits) atomicOr(&g_mask[stage], bits);
}

// ---------------- heavy accel kernel ----------------
__global__ void __launch_bounds__(TPB, 1) stageBK(
    const float* __restrict__ W1L, const float* __restrict__ b1L,
    const float* __restrict__ W2L, const float* __restrict__ b2L,
    const float* __restrict__ W3L, const float* __restrict__ b3L,
    const float* __restrict__ W1V, const float* __restrict__ b1V,
    const float* __restrict__ W2V, const float* __restrict__ b2V,
    const float* __restrict__ W3V, const float* __restrict__ action,
    const float* __restrict__ obs, float* __restrict__ out,
    int stage)
{
    extern __shared__ float s[];
    const int tid = threadIdx.x;

    // stage weights into shared
    for (int i = tid; i < 12*H; i += TPB) s[OFF_S1L + (i%12)*H + i/12] = W1L[i];
    for (int i = tid; i < H*H;  i += TPB) s[OFF_S2L + (i%H)*H + i/H]  = W2L[i];
    for (int i = tid; i < 21*H; i += TPB) s[OFF_S3L + (i%H)*21 + i/H] = W3L[i];
    for (int i = tid; i < 12*H; i += TPB) s[OFF_S1V + (i%12)*H + i/12] = W1V[i];
    for (int i = tid; i < H*H;  i += TPB){
        int m = i / H, k = i % H;
        s[OFF_S2VO + m*130 + k] = W2V[i];   // original [out][in], even stride 130
    }
    for (int i = tid; i < H; i += TPB){
        s[OFF_B1L+i]=b1L[i]; s[OFF_B2L+i]=b2L[i];
        s[OFF_B1V+i]=b1V[i]; s[OFF_B2V+i]=b2V[i];
        s[OFF_W3V+i]=W3V[i];
    }
    for (int i = tid; i < 21; i += TPB) s[OFF_B3L+i]=b3L[i];
    __syncthreads();

    const unsigned mask = g_mask[stage];
    const int wid = tid >> 5, lane = tid & 31;
    float* scr   = s + WTOT + wid*SCR;
    float* vecs  = scr;
    float* ydy   = scr + 896;
    float* dmj   = scr + 1043;
    float* psm   = scr + 1169;
    float* gsm   = scr + 1190;
    float* rhssm = scr + 1196;
    float* qsh   = scr + 1202;
    float* qdsh  = scr + 1208;
    float* tcsm  = scr + 1214;
    float* tssm  = scr + 1220;
    const int o0 = lane*4;
    float* kout = g_kqd[stage];

    for (int e = blockIdx.x*WARPS + wid; e < BATCH; e += gridDim.x*WARPS){
        if (lane < 6){
            float qv  = g_qs[e*6+lane];
            float qdv = g_qds[e*6+lane];
            qsh[lane]  = qv;
            qdsh[lane] = qdv;
            float sn, cs;
            __sincosf(qv, &sn, &cs);
            tcsm[lane] = cs;
            tssm[lane] = sn;
        }
        __syncwarp();
        float tc[6], tsn[6], qdr[6];
        #pragma unroll
        for (int i = 0; i < 6; i++){ tc[i]=tcsm[i]; tsn[i]=tssm[i]; qdr[i]=qdsh[i]; }

        // ==================== L network ====================
        // ---- layer 1: value + 6 tangents (pair-interleaved layout)
        {
            float zz[4];
            #pragma unroll
            for (int m=0;m<4;m++) zz[m] = s[OFF_B1L+o0+m];
            #pragma unroll
            for (int k=0;k<12;k++){
                float tk = (k&1) ? tsn[k>>1] : tc[k>>1];
                float4 w = *(const float4*)&s[OFF_S1L + k*H + o0];
                zz[0]+=w.x*tk; zz[1]+=w.y*tk; zz[2]+=w.z*tk; zz[3]+=w.w*tk;
            }
            float s1[4];
            #pragma unroll
            for (int m=0;m<4;m++){
                float spv, sgv; spsig(zz[m], spv, sgv);
                vecs[o0+m] = spv; s1[m] = sgv;
            }
            #pragma unroll
            for (int p=0;p<3;p++){
                int ja = 2*p, jb = 2*p+1;
                float4 waA = *(const float4*)&s[OFF_S1L + (2*ja  )*H + o0];
                float4 wbA = *(const float4*)&s[OFF_S1L + (2*ja+1)*H + o0];
                float4 waB = *(const float4*)&s[OFF_S1L + (2*jb  )*H + o0];
                float4 wbB = *(const float4*)&s[OFF_S1L + (2*jb+1)*H + o0];
                float ca=tc[ja], sa=tsn[ja], cb=tc[jb], sb=tsn[jb];
                float tav[4], tbv[4];
                tav[0]=s1[0]*(wbA.x*ca - waA.x*sa); tbv[0]=s1[0]*(wbB.x*cb - waB.x*sb);
                tav[1]=s1[1]*(wbA.y*ca - waA.y*sa); tbv[1]=s1[1]*(wbB.y*cb - waB.y*sb);
                tav[2]=s1[2]*(wbA.z*ca - waA.z*sa); tbv[2]=s1[2]*(wbB.z*cb - waB.z*sb);
                tav[3]=s1[3]*(wbA.w*ca - waA.w*sa); tbv[3]=s1[3]*(wbB.w*cb - waB.w*sb);
                *(float4*)&vecs[128 + p*256 + 2*o0]     = make_float4(tav[0],tbv[0],tav[1],tbv[1]);
                *(float4*)&vecs[128 + p*256 + 2*o0 + 4] = make_float4(tav[2],tbv[2],tav[3],tbv[3]);
            }
        }
        __syncwarp();

        // ---- layer 2: value scalar + 3 tangent-pair FFMA2 accumulators
        {
            float a0[4];
            #pragma unroll
            for (int m=0;m<4;m++) a0[m] = s[OFF_B2L+o0+m];
            ull accp[3][4];
            #pragma unroll
            for (int p=0;p<3;p++){
                #pragma unroll
                for (int m=0;m<4;m++) accp[p][m]=0ull;
            }
            for (int k=0;k<H;k+=4){
                float4 hval = *(const float4*)&vecs[k];
                ulonglong2 hA[3], hB[3];
                #pragma unroll
                for (int p=0;p<3;p++){
                    hA[p] = *(const ulonglong2*)&vecs[128 + p*256 + 2*k];
                    hB[p] = *(const ulonglong2*)&vecs[128 + p*256 + 2*k + 4];
                }
                #pragma unroll
                for (int kk=0;kk<4;kk++){
                    float4 w = *(const float4*)&s[OFF_S2L + (k+kk)*H + o0];
                    float hs = (&hval.x)[kk];
                    a0[0] += w.x*hs; a0[1] += w.y*hs; a0[2] += w.z*hs; a0[3] += w.w*hs;
                    ull hp0 = (kk==0)? hA[0].x : (kk==1)? hA[0].y : (kk==2)? hB[0].x : hB[0].y;
                    ull hp1 = (kk==0)? hA[1].x : (kk==1)? hA[1].y : (kk==2)? hB[1].x : hB[1].y;
                    ull hp2 = (kk==0)? hA[2].x : (kk==1)? hA[2].y : (kk==2)? hB[2].x : hB[2].y;
                    #pragma unroll
                    for (int m=0;m<4;m++){
                        float wm = (&w.x)[m];
                        ull wd = pk2(wm, wm);
                        accp[0][m] = ffma2(wd, hp0, accp[0][m]);
                        accp[1][m] = ffma2(wd, hp1, accp[1][m]);
                        accp[2][m] = ffma2(wd, hp2, accp[2][m]);
                    }
                }
            }
            __syncwarp();
            float s2[4];
            #pragma unroll
            for (int m=0;m<4;m++){
                float spv, sgv; spsig(a0[m], spv, sgv);
                vecs[o0+m] = spv; s2[m] = sgv;
            }
            #pragma unroll
            for (int p=0;p<3;p++){
                float tav[4], tbv[4];
                #pragma unroll
                for (int m=0;m<4;m++){
                    float xa, xb; upk2(accp[p][m], xa, xb);
                    tav[m] = s2[m]*xa; tbv[m] = s2[m]*xb;
                }
                *(float4*)&vecs[128 + p*256 + 2*o0]     = make_float4(tav[0],tbv[0],tav[1],tbv[1]);
                *(float4*)&vecs[128 + p*256 + 2*o0 + 4] = make_float4(tav[2],tbv[2],tav[3],tbv[3]);
            }
        }
        __syncwarp();

        // ---- layer 3 (21 outputs), FFMA2-packed tangent pairs
        if (lane < 21){
            float f0 = s[OFF_B3L+lane];
            ull fp[3];
            fp[0]=0ull; fp[1]=0ull; fp[2]=0ull;
            for (int k=0;k<H;k+=4){
                float w0 = s[OFF_S3L+(k+0)*21+lane];
                float w1 = s[OFF_S3L+(k+1)*21+lane];
                float w2 = s[OFF_S3L+(k+2)*21+lane];
                float w3 = s[OFF_S3L+(k+3)*21+lane];
                float4 h4 = *(const float4*)&vecs[k];
                f0 += w0*h4.x + w1*h4.y + w2*h4.z + w3*h4.w;
                ull wd0 = pk2(w0,w0), wd1 = pk2(w1,w1);
                ull wd2 = pk2(w2,w2), wd3 = pk2(w3,w3);
                #pragma unroll
                for (int p=0;p<3;p++){
                    ulonglong2 G0 = *(const ulonglong2*)&vecs[128 + p*256 + 2*k];
                    ulonglong2 G1 = *(const ulonglong2*)&vecs[128 + p*256 + 2*k + 4];
                    fp[p] = ffma2(wd0, G0.x, fp[p]);
                    fp[p] = ffma2(wd1, G0.y, fp[p]);
                    fp[p] = ffma2(wd2, G1.x, fp[p]);
                    fp[p] = ffma2(wd3, G1.y, fp[p]);
                }
            }
            float spv, s3; spsig(f0, spv, s3);
            ydy[lane] = spv;
            #pragma unroll
            for (int p=0;p<3;p++){
                float xa, xb; upk2(fp[p], xa, xb);
                ydy[(1+2*p)*21+lane] = s3*xa;
                ydy[(2+2*p)*21+lane] = s3*xb;
            }
        }
        __syncwarp();

        // ==================== V network (reverse-mode gradient, FFMA2) ====================
        // ---- layer 1: value only; h1 -> vecs[0..128), sv1 -> vecs[128..256)
        {
            float zz[4];
            #pragma unroll
            for (int m=0;m<4;m++) zz[m] = s[OFF_B1V+o0+m];
            #pragma unroll
            for (int k=0;k<12;k++){
                float tk = (k&1) ? tsn[k>>1] : tc[k>>1];
                float4 w = *(const float4*)&s[OFF_S1V + k*H + o0];
                zz[0]+=w.x*tk; zz[1]+=w.y*tk; zz[2]+=w.z*tk; zz[3]+=w.w*tk;
            }
            #pragma unroll
            for (int m=0;m<4;m++){
                float spv, sgv; spsig(zz[m], spv, sgv);
                vecs[o0+m]       = spv;
                vecs[128+o0+m]   = sgv;
            }
        }
        __syncwarp();

        // ---- layer 2 forward (value only), FFMA2 k-pairs: lane owns m = lane+32t
        {
            ull acc2[4];
            #pragma unroll
            for (int t=0;t<4;t++) acc2[t] = pk2(s[OFF_B2V + lane + 32*t], 0.0f);
            for (int k=0;k<H;k+=4){
                ulonglong2 hp = *(const ulonglong2*)&vecs[k];
                #pragma unroll
                for (int t=0;t<4;t++){
                    const float* row = &s[OFF_S2VO + (lane+32*t)*130];
                    ull w01 = *(const ull*)&row[k];
                    ull w23 = *(const ull*)&row[k+2];
                    acc2[t] = ffma2(w01, hp.x, acc2[t]);
                    acc2[t] = ffma2(w23, hp.y, acc2[t]);
                }
            }
            // a2s[m] = W3V[m] * sigmoid(z2[m]) -> vecs[256..384)
            #pragma unroll
            for (int t=0;t<4;t++)
                vecs[256 + lane + 32*t] = s[OFF_W3V + lane + 32*t] * sig_f(hsum2(acc2[t]));
        }
        __syncwarp();

        // ---- layer 2 backward (FFMA2 k-pairs): lane owns k-pairs {2*lane+64p, +1}
        ull a1p[2];
        {
            ull gacc[2] = {0ull, 0ull};
            for (int m=0;m<H;m+=2){
                float b0 = vecs[256+m];
                float b1v = vecs[256+m+1];
                ull bd0 = pk2(b0,b0), bd1 = pk2(b1v,b1v);
                #pragma unroll
                for (int p=0;p<2;p++){
                    int kk = 2*lane + 64*p;
                    gacc[p] = ffma2(*(const ull*)&s[OFF_S2VO + (m  )*130 + kk], bd0, gacc[p]);
                    gacc[p] = ffma2(*(const ull*)&s[OFF_S2VO + (m+1)*130 + kk], bd1, gacc[p]);
                }
            }
            // a1[k] = gb[k]*sv1[k] (packed)
            #pragma unroll
            for (int p=0;p<2;p++){
                ull sv = *(const ull*)&vecs[128 + 2*lane + 64*p];
                a1p[p] = ffma2(gacc[p], sv, 0ull);
            }
        }

        // ---- gravity: g_j = sum_k a1[k]*(W1V[k][2j+1]c_j - W1V[k][2j]s_j), packed
        {
            #pragma unroll
            for (int j=0;j<6;j++){
                float cj=tc[j], sj=tsn[j];
                ull cjd = pk2(cj,cj), sjd = pk2(-sj,-sj);
                ull gp = 0ull;
                #pragma unroll
                for (int p=0;p<2;p++){
                    int kk = 2*lane + 64*p;
                    ull wb = *(const ull*)&s[OFF_S1V + (2*j+1)*H + kk];
                    ull wa = *(const ull*)&s[OFF_S1V + (2*j  )*H + kk];
                    ull val = ffma2(wa, sjd, ffma2(wb, cjd, 0ull));
                    gp = ffma2(a1p[p], val, gp);
                }
                float g = wsum(hsum2(gp));
                if (lane == 0) gsm[j] = g;
            }
        }
        __syncwarp();

        // ---- dM_j lower-tri entries
        for (int t = lane; t < 126; t += 32){
            int j = t/21, u = t%21;
            int a = c_TI[u], b = c_TJ[u];
            int ta = a*(a+1)/2, tb = b*(b+1)/2;
            const float* Lr = ydy;
            const float* Dr = ydy + (j+1)*21;
            float sacc = 0.f;
            for (int m = 0; m <= b; m++)
                sacc += Dr[ta+m]*Lr[tb+m] + Lr[ta+m]*Dr[tb+m];
            dmj[t] = sacc;
        }
        __syncwarp();

        // ---- P = sum_j qdot_j dM_j
        if (lane < 21){
            float p = 0.f;
            #pragma unroll
            for (int j=0;j<6;j++) p += qdr[j]*dmj[j*21+lane];
            psm[lane] = p;
        }
        __syncwarp();

        // ---- c_i, constraints, rhs
        if (lane < 6){
            int i = lane;
            float c1 = 0.f;
            #pragma unroll
            for (int b=0;b<6;b++){
                int idx = (i >= b) ? (i*(i+1)/2 + b) : (b*(b+1)/2 + i);
                c1 += psm[idx]*qdr[b];
            }
            float qf = 0.f;   // 0.5 * qd^T dM_i qd
            for (int u2=0; u2<21; u2++){
                int a = c_TI[u2], b = c_TJ[u2];
                float w = (a==b) ? 0.5f : 1.0f;
                qf += w*dmj[i*21+u2]*qdsh[a]*qdsh[b];
            }
            float ci = c1 - qf;
            float qi = qsh[i];
            float lo = c_LOWER[i] + 0.1f;
            float up = c_UPPER[i] - 0.1f;
            float fi;
            if (mask & (1u << i))
                fi = (qi <= lo) ? c_EFFORT[i] : ((qi >= up) ? -c_EFFORT[i] : 0.0f);
            else
                fi = -5.0f*(__fdividef(1.0f, qi-lo) - __fdividef(1.0f, up-qi));
            float tau = action[e*6+i]*c_EFFORT[i];
            rhssm[i] = tau - ci - gsm[i] - fi;
        }
        __syncwarp();

        // ---- solve (L L^T) x = rhs; stage 3 also does the final RK4 combine
        if (lane == 0){
            float Lm[6][6];
            #pragma unroll
            for (int i=0;i<6;i++){
                #pragma unroll
                for (int jj=0;jj<6;jj++)
                    Lm[i][jj] = (jj<=i) ? ydy[i*(i+1)/2+jj] : 0.f;
            }
            float rinv[6];
            #pragma unroll
            for (int i=0;i<6;i++) rinv[i] = __fdividef(1.0f, Lm[i][i]);
            float wv[6], x[6];
            #pragma unroll
            for (int i=0;i<6;i++){
                float sr = rhssm[i];
                #pragma unroll
                for (int jj=0;jj<6;jj++) if (jj < i) sr -= Lm[i][jj]*wv[jj];
                wv[i] = sr * rinv[i];
            }
            #pragma unroll
            for (int i=5;i>=0;i--){
                float sr = wv[i];
                #pragma unroll
                for (int jj=0;jj<6;jj++) if (jj > i) sr -= Lm[jj][i]*x[jj];
                x[i] = sr * rinv[i];
            }
            if (stage < 3){
                #pragma unroll
                for (int i=0;i<6;i++) kout[e*6+i] = x[i];
            } else {
                // fused final RK4 combine (k4 = x)
                #pragma unroll
                for (int i=0;i<6;i++){
                    float q  = obs[e*12 + i];
                    float qd = obs[e*12 + 6 + i];
                    float k1 = g_kqd[0][e*6+i];
                    float k2 = g_kqd[1][e*6+i];
                    float k3 = g_kqd[2][e*6+i];
                    float k4 = x[i];
                    float k1q = qd;
                    float k2q = qd + 0.5f*DTc*k1;
                    float k3q = qd + 0.5f*DTc*k2;
                    float k4q = qd + DTc*k3;
                    float qn  = q  + (DTc/6.0f)*(k1q + 2.f*k2q + 2.f*k3q + k4q);
                    float qdn = qd + (DTc/6.0f)*(k1  + 2.f*k2  + 2.f*k3  + k4 );
                    qn = fminf(fmaxf(qn, c_LOWER[i]), c_UPPER[i]);
                    out[e*12 + i]     = qn;
                    out[e*12 + 6 + i] = qdn;
                }
            }
        }
        __syncwarp();
    }
}

extern "C" void kernel_launch(void* const* d_in, const int* in_sizes, int n_in,
                              void* d_out, int out_size)
{
    const float* obs    = (const float*)d_in[0];
    const float* action = (const float*)d_in[1];
    const float* W1L = (const float*)d_in[2];  const float* b1L = (const float*)d_in[3];
    const float* W2L = (const float*)d_in[4];  const float* b2L = (const float*)d_in[5];
    const float* W3L = (const float*)d_in[6];  const float* b3L = (const float*)d_in[7];
    const float* W1V = (const float*)d_in[8];  const float* b1V = (const float*)d_in[9];
    const float* W2V = (const float*)d_in[10]; const float* b2V = (const float*)d_in[11];
    const float* W3V = (const float*)d_in[12];
    float* out = (float*)d_out;

    cudaFuncSetAttribute(stageBK, cudaFuncAttributeMaxDynamicSharedMemorySize, SMEM_BYTES);

    zeroMaskK<<<1, 32>>>();
    for (int st = 0; st < 4; st++){
        stageAK<<<BATCH/256, 256>>>(obs, st);
        stageBK<<<NBLK, TPB, SMEM_BYTES>>>(W1L,b1L,W2L,b2L,W3L,b3L,
                                           W1V,b1V,W2V,b2V,W3V, action,
                                           obs, out, st);
    }
}